// round 1
// baseline (speedup 1.0000x reference)
#include <cuda_runtime.h>
#include <math.h>

// ---------------------------------------------------------------------------
// SimpleCNN (DCLS) forward, B=4096, fp32 baseline
//   scratch: __device__ globals (no allocations, graph-capturable)
// ---------------------------------------------------------------------------

#define B_MAX 4096

__device__ float g_K1[32 * 36];            // (32,1) filters as 6x6 grids
__device__ float g_K2[64 * 32 * 36];       // (64,32) filters as 6x6 grids
__device__ float g_h1[B_MAX * 32 * 14 * 14];
__device__ float g_h2[B_MAX * 64 * 7 * 7];
__device__ float g_fc1[B_MAX * 128];

// ---------------- kernel construction (DCLS bilinear scatter) --------------

__global__ void zero_k() {
    int i = blockIdx.x * blockDim.x + threadIdx.x;
    if (i < 32 * 36) g_K1[i] = 0.f;
    if (i < 64 * 32 * 36) g_K2[i] = 0.f;
}

__device__ __forceinline__ void dcls_scatter(float* grid, float w, float pa, float pb) {
    float p1c = fminf(fmaxf(pa, -2.f), 2.f) + 2.f;   // [0,4]
    float p2c = fminf(fmaxf(pb, -2.f), 2.f) + 2.f;
    int i1 = (int)floorf(p1c);
    int i2 = (int)floorf(p2c);
    float r1 = p1c - (float)i1;
    float r2 = p2c - (float)i2;
    atomicAdd(&grid[i1 * 6 + i2],           w * (1.f - r1) * (1.f - r2));
    atomicAdd(&grid[(i1 + 1) * 6 + i2],     w * r1 * (1.f - r2));
    atomicAdd(&grid[i1 * 6 + i2 + 1],       w * (1.f - r1) * r2);
    atomicAdd(&grid[(i1 + 1) * 6 + i2 + 1], w * r1 * r2);
}

__global__ void build_k(const float* __restrict__ w1, const float* __restrict__ p1,
                        const float* __restrict__ w2, const float* __restrict__ p2) {
    int idx = blockIdx.x * blockDim.x + threadIdx.x;
    if (idx < 512) {                       // w1: (32,1,16)
        float w = w1[idx];
        int f = idx / 16;                  // oc (Cin=1)
        dcls_scatter(g_K1 + f * 36, w, p1[idx], p1[512 + idx]);
    } else if (idx < 512 + 65536) {        // w2: (64,32,32)
        int e = idx - 512;
        float w = w2[e];
        int f = e / 32;                    // oc*32+ic
        dcls_scatter(g_K2 + f * 36, w, p2[e], p2[65536 + e]);
    }
}

// ---------------- conv1 + bias + relu + maxpool2 ---------------------------
// x: (B,1,28,28) -> g_h1: (B,32,14,14). One image per CTA.

__global__ void conv1_kernel(const float* __restrict__ x, const float* __restrict__ b1) {
    __shared__ float sIn[32 * 32];   // 28x28 padded by 2 -> 32x32
    __shared__ float sW[32 * 25];
    __shared__ float sB[32];
    int tid = threadIdx.x;
    int b = blockIdx.x;

    for (int i = tid; i < 1024; i += 256) sIn[i] = 0.f;
    __syncthreads();
    const float* xi = x + b * 784;
    for (int i = tid; i < 784; i += 256) {
        int y = i / 28, c = i % 28;
        sIn[(y + 2) * 32 + c + 2] = xi[i];
    }
    for (int i = tid; i < 800; i += 256) {
        int oc = i / 25, t = i % 25;
        sW[i] = g_K1[oc * 36 + (t / 5) * 6 + (t % 5)];
    }
    if (tid < 32) sB[tid] = b1[tid];
    __syncthreads();

    for (int idx = tid; idx < 32 * 196; idx += 256) {
        int oc = idx / 196, s = idx % 196;
        int py = s / 14, px = s % 14;
        int Y = 2 * py, X = 2 * px;
        float win[6][6];
#pragma unroll
        for (int a = 0; a < 6; a++)
#pragma unroll
            for (int c = 0; c < 6; c++) win[a][c] = sIn[(Y + a) * 32 + X + c];
        const float* wp = sW + oc * 25;
        float a00 = 0.f, a01 = 0.f, a10 = 0.f, a11 = 0.f;
#pragma unroll
        for (int dy = 0; dy < 5; dy++)
#pragma unroll
            for (int dx = 0; dx < 5; dx++) {
                float w = wp[dy * 5 + dx];
                a00 += win[dy][dx] * w;
                a01 += win[dy][dx + 1] * w;
                a10 += win[dy + 1][dx] * w;
                a11 += win[dy + 1][dx + 1] * w;
            }
        float m = fmaxf(fmaxf(a00, a01), fmaxf(a10, a11)) + sB[oc];
        g_h1[b * 6272 + idx] = fmaxf(m, 0.f);
    }
}

// ---------------- conv2 + bias + relu + maxpool2 ---------------------------
// g_h1: (B,32,14,14) -> g_h2: (B,64,7,7). One image per CTA, 16-oc weight
// chunks in SMEM, each thread: one pool site x 4 output channels.

#define CONV2_SMEM ((32 * 324 + 16 * 32 * 25) * 4)

__global__ void conv2_kernel(const float* __restrict__ b2) {
    extern __shared__ float smem[];
    float* sIn = smem;                 // 32 ch x 18x18 padded
    float* sW  = smem + 32 * 324;      // 16 oc x 32 ic x 25
    int tid = threadIdx.x;
    int b = blockIdx.x;

    for (int i = tid; i < 32 * 324; i += 256) sIn[i] = 0.f;
    __syncthreads();
    const float* hi = g_h1 + b * 6272;
    for (int i = tid; i < 6272; i += 256) {
        int ic = i / 196, s = i % 196;
        int y = s / 14, xx = s % 14;
        sIn[ic * 324 + (y + 2) * 18 + xx + 2] = hi[i];
    }

    for (int oc0 = 0; oc0 < 64; oc0 += 16) {
        __syncthreads();   // input fill done / previous chunk compute done
        for (int i = tid; i < 16 * 32 * 25; i += 256) {
            int t = i % 25;
            int rem = i / 25;          // oc_l*32 + ic
            sW[i] = g_K2[(oc0 * 32 + rem) * 36 + (t / 5) * 6 + (t % 5)];
        }
        __syncthreads();

        for (int idx = tid; idx < 196; idx += 256) {
            int g = idx / 49, site = idx % 49;
            int py = site / 7, px = site % 7;
            int Y = 2 * py, X = 2 * px;
            float a00[4] = {0.f, 0.f, 0.f, 0.f};
            float a01[4] = {0.f, 0.f, 0.f, 0.f};
            float a10[4] = {0.f, 0.f, 0.f, 0.f};
            float a11[4] = {0.f, 0.f, 0.f, 0.f};
#pragma unroll 1
            for (int ic = 0; ic < 32; ic++) {
                const float* ip = sIn + ic * 324 + Y * 18 + X;
                float win[6][6];
#pragma unroll
                for (int a = 0; a < 6; a++)
#pragma unroll
                    for (int c = 0; c < 6; c++) win[a][c] = ip[a * 18 + c];
#pragma unroll
                for (int j = 0; j < 4; j++) {
                    const float* wp = sW + ((g * 4 + j) * 32 + ic) * 25;
#pragma unroll
                    for (int dy = 0; dy < 5; dy++)
#pragma unroll
                        for (int dx = 0; dx < 5; dx++) {
                            float w = wp[dy * 5 + dx];
                            a00[j] += win[dy][dx] * w;
                            a01[j] += win[dy][dx + 1] * w;
                            a10[j] += win[dy + 1][dx] * w;
                            a11[j] += win[dy + 1][dx + 1] * w;
                        }
                }
            }
#pragma unroll
            for (int j = 0; j < 4; j++) {
                int oc = oc0 + g * 4 + j;
                float m = fmaxf(fmaxf(a00[j], a01[j]), fmaxf(a10[j], a11[j])) + b2[oc];
                g_h2[b * 3136 + oc * 49 + site] = fmaxf(m, 0.f);
            }
        }
    }
}

// ---------------- FC1: (B,3136) @ (128,3136)^T + bias, relu ----------------
// Classic SMEM-tiled SGEMM: BM=BN=64, BK=16, 256 threads, 4x4 micro-tile.

__global__ void fc1_kernel(const float* __restrict__ W, const float* __restrict__ bias) {
    __shared__ float As[16][64];
    __shared__ float Bs[16][64];
    int tid = threadIdx.x;
    int tx = tid % 16, ty = tid / 16;
    int row0 = blockIdx.x * 64, col0 = blockIdx.y * 64;
    float acc[4][4] = {};
    int lm = tid / 4;
    int lk = (tid % 4) * 4;
    const float* Arow = g_h2 + (size_t)(row0 + lm) * 3136 + lk;
    const float* Brow = W + (size_t)(col0 + lm) * 3136 + lk;

    for (int kt = 0; kt < 3136; kt += 16) {
        float4 av = *(const float4*)(Arow + kt);
        float4 bv = *(const float4*)(Brow + kt);
        As[lk + 0][lm] = av.x; As[lk + 1][lm] = av.y;
        As[lk + 2][lm] = av.z; As[lk + 3][lm] = av.w;
        Bs[lk + 0][lm] = bv.x; Bs[lk + 1][lm] = bv.y;
        Bs[lk + 2][lm] = bv.z; Bs[lk + 3][lm] = bv.w;
        __syncthreads();
#pragma unroll
        for (int k = 0; k < 16; k++) {
            float ra[4], rb[4];
#pragma unroll
            for (int i = 0; i < 4; i++) { ra[i] = As[k][ty * 4 + i]; rb[i] = Bs[k][tx * 4 + i]; }
#pragma unroll
            for (int i = 0; i < 4; i++)
#pragma unroll
                for (int j = 0; j < 4; j++) acc[i][j] += ra[i] * rb[j];
        }
        __syncthreads();
    }
#pragma unroll
    for (int i = 0; i < 4; i++) {
        int r = row0 + ty * 4 + i;
#pragma unroll
        for (int j = 0; j < 4; j++) {
            int c = col0 + tx * 4 + j;
            g_fc1[r * 128 + c] = fmaxf(acc[i][j] + bias[c], 0.f);
        }
    }
}

// ---------------- FC2: (B,128) @ (10,128)^T + bias -------------------------
// One warp per image; lanes split K, warp-reduce 10 outputs.

__global__ void fc2_kernel(const float* __restrict__ W, const float* __restrict__ bias,
                           float* __restrict__ out, int B) {
    int warp = (blockIdx.x * blockDim.x + threadIdx.x) / 32;
    int lane = threadIdx.x % 32;
    if (warp >= B) return;
    const float* h = g_fc1 + warp * 128;
    float v0 = h[lane], v1 = h[32 + lane], v2 = h[64 + lane], v3 = h[96 + lane];
    float acc[10];
#pragma unroll
    for (int o = 0; o < 10; o++) {
        const float* w = W + o * 128;
        float a = v0 * w[lane] + v1 * w[32 + lane] + v2 * w[64 + lane] + v3 * w[96 + lane];
#pragma unroll
        for (int off = 16; off > 0; off >>= 1)
            a += __shfl_xor_sync(0xFFFFFFFF, a, off);
        acc[o] = a;
    }
    if (lane == 0) {
#pragma unroll
        for (int o = 0; o < 10; o++) out[warp * 10 + o] = acc[o] + bias[o];
    }
}

// ---------------------------------------------------------------------------

extern "C" void kernel_launch(void* const* d_in, const int* in_sizes, int n_in,
                              void* d_out, int out_size) {
    const float* x    = (const float*)d_in[0];
    const float* w1   = (const float*)d_in[1];
    const float* p1   = (const float*)d_in[2];
    const float* b1   = (const float*)d_in[3];
    const float* w2   = (const float*)d_in[4];
    const float* p2   = (const float*)d_in[5];
    const float* b2   = (const float*)d_in[6];
    const float* fc1w = (const float*)d_in[7];
    const float* fc1b = (const float*)d_in[8];
    const float* fc2w = (const float*)d_in[9];
    const float* fc2b = (const float*)d_in[10];
    float* out = (float*)d_out;

    int B = in_sizes[0] / 784;
    if (B > B_MAX) B = B_MAX;

    zero_k<<<(64 * 32 * 36 + 255) / 256, 256>>>();
    build_k<<<(512 + 65536 + 255) / 256, 256>>>(w1, p1, w2, p2);
    conv1_kernel<<<B, 256>>>(x, b1);

    cudaFuncSetAttribute(conv2_kernel, cudaFuncAttributeMaxDynamicSharedMemorySize, CONV2_SMEM);
    conv2_kernel<<<B, 256, CONV2_SMEM>>>(b2);

    dim3 g1(B / 64, 2);
    fc1_kernel<<<g1, 256>>>(fc1w, fc1b);
    fc2_kernel<<<(B * 32 + 255) / 256, 256>>>(fc2w, fc2b, out, B);
}

// round 2
// speedup vs baseline: 1.8149x; 1.8149x over previous
#include <cuda_runtime.h>
#include <math.h>

// ---------------------------------------------------------------------------
// SimpleCNN (DCLS) forward, B=4096.
// R2: conv layers rewritten around packed fma.rn.f32x2 (2 output channels per
// 64-bit accumulator) + pool-row-per-thread tiling (input LDS broadcast).
// ---------------------------------------------------------------------------

#define B_MAX 4096

__device__ float g_K1[32 * 36];            // (32,1) filters as 6x6 grids
__device__ float g_K2[64 * 32 * 36];       // (64,32) filters as 6x6 grids
__device__ float2 g_W1p[25 * 16];          // [tap][pair] packed oc-pairs
__device__ float2 g_W2p[32 * 25 * 32];     // [ic][tap][pairGlobal]
__device__ float g_h1[B_MAX * 32 * 14 * 14];
__device__ float g_h2[B_MAX * 64 * 7 * 7];
__device__ float g_fc1[B_MAX * 128];

// Packed dual-FMA: d = a*b + d on two f32 lanes (sm_103a FFMA2)
__device__ __forceinline__ void fma2(float2& d, const float2& a, const float2& b) {
    asm("fma.rn.f32x2 %0, %1, %2, %0;"
        : "+l"(reinterpret_cast<unsigned long long&>(d))
        : "l"(reinterpret_cast<const unsigned long long&>(a)),
          "l"(reinterpret_cast<const unsigned long long&>(b)));
}

// ---------------- kernel construction (DCLS bilinear scatter) --------------

__global__ void zero_k() {
    int i = blockIdx.x * blockDim.x + threadIdx.x;
    if (i < 32 * 36) g_K1[i] = 0.f;
    if (i < 64 * 32 * 36) g_K2[i] = 0.f;
}

__device__ __forceinline__ void dcls_scatter(float* grid, float w, float pa, float pb) {
    float p1c = fminf(fmaxf(pa, -2.f), 2.f) + 2.f;   // [0,4]
    float p2c = fminf(fmaxf(pb, -2.f), 2.f) + 2.f;
    int i1 = (int)floorf(p1c);
    int i2 = (int)floorf(p2c);
    float r1 = p1c - (float)i1;
    float r2 = p2c - (float)i2;
    atomicAdd(&grid[i1 * 6 + i2],           w * (1.f - r1) * (1.f - r2));
    atomicAdd(&grid[(i1 + 1) * 6 + i2],     w * r1 * (1.f - r2));
    atomicAdd(&grid[i1 * 6 + i2 + 1],       w * (1.f - r1) * r2);
    atomicAdd(&grid[(i1 + 1) * 6 + i2 + 1], w * r1 * r2);
}

__global__ void build_k(const float* __restrict__ w1, const float* __restrict__ p1,
                        const float* __restrict__ w2, const float* __restrict__ p2) {
    int idx = blockIdx.x * blockDim.x + threadIdx.x;
    if (idx < 512) {                       // w1: (32,1,16)
        float w = w1[idx];
        int f = idx / 16;
        dcls_scatter(g_K1 + f * 36, w, p1[idx], p1[512 + idx]);
    } else if (idx < 512 + 65536) {        // w2: (64,32,32)
        int e = idx - 512;
        float w = w2[e];
        int f = e / 32;                    // oc*32+ic
        dcls_scatter(g_K2 + f * 36, w, p2[e], p2[65536 + e]);
    }
}

// Repack 6x6 grids into oc-pair-packed 5x5 weight tables.
__global__ void repack_k() {
    int i = blockIdx.x * blockDim.x + threadIdx.x;
    if (i < 400) {                          // W1p: [tap25][pair16]
        int t = i / 16, p = i % 16;
        int tap = (t / 5) * 6 + (t % 5);
        g_W1p[i] = make_float2(g_K1[(2 * p) * 36 + tap], g_K1[(2 * p + 1) * 36 + tap]);
    }
    if (i < 25600) {                        // W2p: [ic32][tap25][pair32]
        int ic = i / 800, r = i % 800;
        int t = r / 32, pg = r % 32;
        int tap = (t / 5) * 6 + (t % 5);
        g_W2p[i] = make_float2(g_K2[((2 * pg) * 32 + ic) * 36 + tap],
                               g_K2[((2 * pg + 1) * 32 + ic) * 36 + tap]);
    }
}

// ---------------- conv1 + bias + relu + maxpool2 ---------------------------
// x:(B,1,28,28) -> g_h1:(B,32,14,14). CTA=image, 448 thr =
// 16 oc-pairs x 14 pool-rows x 2 x-halves. Each thread: 2x14 pre-pool row,
// packed over 2 oc.

__global__ __launch_bounds__(448, 1) void conv1_kernel(const float* __restrict__ x,
                                                       const float* __restrict__ b1) {
    __shared__ float sIn[32 * 32];
    __shared__ float2 sW[25 * 16];    // [tap][pair]
    int tid = threadIdx.x;
    int b = blockIdx.x;

    for (int i = tid; i < 1024; i += 448) sIn[i] = 0.f;
    if (tid < 400) sW[tid] = g_W1p[tid];
    __syncthreads();
    const float* xi = x + b * 784;
    for (int i = tid; i < 784; i += 448) {
        int y = i / 28, c = i % 28;
        sIn[(y + 2) * 32 + c + 2] = xi[i];
    }
    __syncthreads();

    int pair = tid & 15;
    int py = (tid >> 4) % 14;
    int xh = tid / 224;
    int Y = 2 * py, X0 = xh * 14;

    float2 acc[2][14];
#pragma unroll
    for (int r = 0; r < 2; r++)
#pragma unroll
        for (int c = 0; c < 14; c++) acc[r][c] = make_float2(0.f, 0.f);

#pragma unroll
    for (int dyy = 0; dyy < 6; dyy++) {
        const float* rp = sIn + (Y + dyy) * 32 + X0;
        float2 vp[18];
#pragma unroll
        for (int i = 0; i < 18; i++) { float v = rp[i]; vp[i] = make_float2(v, v); }
        if (dyy < 5) {
#pragma unroll
            for (int dx = 0; dx < 5; dx++) {
                float2 w = sW[(dyy * 5 + dx) * 16 + pair];
#pragma unroll
                for (int c = 0; c < 14; c++) fma2(acc[0][c], vp[c + dx], w);
            }
        }
        if (dyy >= 1) {
#pragma unroll
            for (int dx = 0; dx < 5; dx++) {
                float2 w = sW[((dyy - 1) * 5 + dx) * 16 + pair];
#pragma unroll
                for (int c = 0; c < 14; c++) fma2(acc[1][c], vp[c + dx], w);
            }
        }
    }

    int oc0 = 2 * pair;
    float blo = b1[oc0], bhi = b1[oc0 + 1];
    float* o0 = g_h1 + b * 6272 + oc0 * 196 + py * 14 + xh * 7;
    float* o1 = o0 + 196;
#pragma unroll
    for (int px = 0; px < 7; px++) {
        float2 q0 = acc[0][2 * px], q1 = acc[0][2 * px + 1];
        float2 q2 = acc[1][2 * px], q3 = acc[1][2 * px + 1];
        float mlo = fmaxf(fmaxf(q0.x, q1.x), fmaxf(q2.x, q3.x)) + blo;
        float mhi = fmaxf(fmaxf(q0.y, q1.y), fmaxf(q2.y, q3.y)) + bhi;
        o0[px] = fmaxf(mlo, 0.f);
        o1[px] = fmaxf(mhi, 0.f);
    }
}

// ---------------- conv2 + bias + relu + maxpool2 ---------------------------
// g_h1:(B,32,14,14) -> g_h2:(B,64,7,7). CTA=(image, oc-half of 32).
// 128 thr, 112 active = 16 pairs x 7 pool-rows. ic chunked by 8 for weights.

#define CONV2_SMEM (32 * 324 * 4 + 8 * 25 * 16 * 8)

__global__ __launch_bounds__(128, 3) void conv2_kernel(const float* __restrict__ b2) {
    extern __shared__ float smem[];
    float* sIn = smem;                               // 32 x 18x18
    float2* sW = (float2*)(smem + 32 * 324);         // [ic8][tap25][pair16]
    int tid = threadIdx.x;
    int b = blockIdx.x;
    int h = blockIdx.y;                              // oc half

    for (int i = tid; i < 32 * 324; i += 128) sIn[i] = 0.f;
    __syncthreads();
    const float* hi = g_h1 + b * 6272;
    for (int i = tid; i < 6272; i += 128) {
        int ic = i / 196, s = i % 196;
        int y = s / 14, xx = s % 14;
        sIn[ic * 324 + (y + 2) * 18 + xx + 2] = hi[i];
    }

    int pair = tid & 15;
    int py = tid >> 4;                               // 0..6 valid (py 7 idle)
    bool active = (py < 7);
    int Y = 2 * py * (active ? 1 : 0);

    float2 acc[2][14];
#pragma unroll
    for (int r = 0; r < 2; r++)
#pragma unroll
        for (int c = 0; c < 14; c++) acc[r][c] = make_float2(0.f, 0.f);

    for (int chunk = 0; chunk < 4; chunk++) {
        __syncthreads();
        // stage weights for 8 ic, 16 pairs of this half
        for (int i = tid; i < 8 * 25 * 16; i += 128) {
            int ic8 = i / 400, r = i % 400;
            int t = r / 16, p = r % 16;
            sW[i] = g_W2p[((chunk * 8 + ic8) * 25 + t) * 32 + h * 16 + p];
        }
        __syncthreads();
        if (!active) continue;

#pragma unroll 1
        for (int ic8 = 0; ic8 < 8; ic8++) {
            const float* icbase = sIn + (chunk * 8 + ic8) * 324;
            float2 wreg[25];
#pragma unroll
            for (int t = 0; t < 25; t++) wreg[t] = sW[(ic8 * 25 + t) * 16 + pair];
#pragma unroll
            for (int dyy = 0; dyy < 6; dyy++) {
                const float* rp = icbase + (Y + dyy) * 18;
                float2 vp[18];
#pragma unroll
                for (int i = 0; i < 18; i++) { float v = rp[i]; vp[i] = make_float2(v, v); }
                if (dyy < 5) {
#pragma unroll
                    for (int dx = 0; dx < 5; dx++) {
                        float2 w = wreg[dyy * 5 + dx];
#pragma unroll
                        for (int c = 0; c < 14; c++) fma2(acc[0][c], vp[c + dx], w);
                    }
                }
                if (dyy >= 1) {
#pragma unroll
                    for (int dx = 0; dx < 5; dx++) {
                        float2 w = wreg[(dyy - 1) * 5 + dx];
#pragma unroll
                        for (int c = 0; c < 14; c++) fma2(acc[1][c], vp[c + dx], w);
                    }
                }
            }
        }
    }
    if (!active) return;

    int oc0 = h * 32 + 2 * pair;
    float blo = b2[oc0], bhi = b2[oc0 + 1];
    float* o0 = g_h2 + b * 3136 + oc0 * 49 + py * 7;
    float* o1 = o0 + 49;
#pragma unroll
    for (int px = 0; px < 7; px++) {
        float2 q0 = acc[0][2 * px], q1 = acc[0][2 * px + 1];
        float2 q2 = acc[1][2 * px], q3 = acc[1][2 * px + 1];
        float mlo = fmaxf(fmaxf(q0.x, q1.x), fmaxf(q2.x, q3.x)) + blo;
        float mhi = fmaxf(fmaxf(q0.y, q1.y), fmaxf(q2.y, q3.y)) + bhi;
        o0[px] = fmaxf(mlo, 0.f);
        o1[px] = fmaxf(mhi, 0.f);
    }
}

// ---------------- FC1: (B,3136) @ (128,3136)^T + bias, relu ----------------

__global__ void fc1_kernel(const float* __restrict__ W, const float* __restrict__ bias) {
    __shared__ float As[16][64];
    __shared__ float Bs[16][64];
    int tid = threadIdx.x;
    int tx = tid % 16, ty = tid / 16;
    int row0 = blockIdx.x * 64, col0 = blockIdx.y * 64;
    float acc[4][4] = {};
    int lm = tid / 4;
    int lk = (tid % 4) * 4;
    const float* Arow = g_h2 + (size_t)(row0 + lm) * 3136 + lk;
    const float* Brow = W + (size_t)(col0 + lm) * 3136 + lk;

    for (int kt = 0; kt < 3136; kt += 16) {
        float4 av = *(const float4*)(Arow + kt);
        float4 bv = *(const float4*)(Brow + kt);
        As[lk + 0][lm] = av.x; As[lk + 1][lm] = av.y;
        As[lk + 2][lm] = av.z; As[lk + 3][lm] = av.w;
        Bs[lk + 0][lm] = bv.x; Bs[lk + 1][lm] = bv.y;
        Bs[lk + 2][lm] = bv.z; Bs[lk + 3][lm] = bv.w;
        __syncthreads();
#pragma unroll
        for (int k = 0; k < 16; k++) {
            float ra[4], rb[4];
#pragma unroll
            for (int i = 0; i < 4; i++) { ra[i] = As[k][ty * 4 + i]; rb[i] = Bs[k][tx * 4 + i]; }
#pragma unroll
            for (int i = 0; i < 4; i++)
#pragma unroll
                for (int j = 0; j < 4; j++) acc[i][j] += ra[i] * rb[j];
        }
        __syncthreads();
    }
#pragma unroll
    for (int i = 0; i < 4; i++) {
        int r = row0 + ty * 4 + i;
#pragma unroll
        for (int j = 0; j < 4; j++) {
            int c = col0 + tx * 4 + j;
            g_fc1[r * 128 + c] = fmaxf(acc[i][j] + bias[c], 0.f);
        }
    }
}

// ---------------- FC2: (B,128) @ (10,128)^T + bias -------------------------

__global__ void fc2_kernel(const float* __restrict__ W, const float* __restrict__ bias,
                           float* __restrict__ out, int B) {
    int warp = (blockIdx.x * blockDim.x + threadIdx.x) / 32;
    int lane = threadIdx.x % 32;
    if (warp >= B) return;
    const float* hh = g_fc1 + warp * 128;
    float v0 = hh[lane], v1 = hh[32 + lane], v2 = hh[64 + lane], v3 = hh[96 + lane];
    float acc[10];
#pragma unroll
    for (int o = 0; o < 10; o++) {
        const float* w = W + o * 128;
        float a = v0 * w[lane] + v1 * w[32 + lane] + v2 * w[64 + lane] + v3 * w[96 + lane];
#pragma unroll
        for (int off = 16; off > 0; off >>= 1)
            a += __shfl_xor_sync(0xFFFFFFFF, a, off);
        acc[o] = a;
    }
    if (lane == 0) {
#pragma unroll
        for (int o = 0; o < 10; o++) out[warp * 10 + o] = acc[o] + bias[o];
    }
}

// ---------------------------------------------------------------------------

extern "C" void kernel_launch(void* const* d_in, const int* in_sizes, int n_in,
                              void* d_out, int out_size) {
    const float* x    = (const float*)d_in[0];
    const float* w1   = (const float*)d_in[1];
    const float* p1   = (const float*)d_in[2];
    const float* b1   = (const float*)d_in[3];
    const float* w2   = (const float*)d_in[4];
    const float* p2   = (const float*)d_in[5];
    const float* b2   = (const float*)d_in[6];
    const float* fc1w = (const float*)d_in[7];
    const float* fc1b = (const float*)d_in[8];
    const float* fc2w = (const float*)d_in[9];
    const float* fc2b = (const float*)d_in[10];
    float* out = (float*)d_out;

    int B = in_sizes[0] / 784;
    if (B > B_MAX) B = B_MAX;

    zero_k<<<(64 * 32 * 36 + 255) / 256, 256>>>();
    build_k<<<(512 + 65536 + 255) / 256, 256>>>(w1, p1, w2, p2);
    repack_k<<<(25600 + 255) / 256, 256>>>();

    conv1_kernel<<<B, 448>>>(x, b1);

    cudaFuncSetAttribute(conv2_kernel, cudaFuncAttributeMaxDynamicSharedMemorySize, CONV2_SMEM);
    dim3 g2(B, 2);
    conv2_kernel<<<g2, 128, CONV2_SMEM>>>(b2);

    dim3 g1(B / 64, 2);
    fc1_kernel<<<g1, 256>>>(fc1w, fc1b);
    fc2_kernel<<<(B * 32 + 255) / 256, 256>>>(fc2w, fc2b, out, B);
}

// round 4
// speedup vs baseline: 2.9296x; 1.6142x over previous
#include <cuda_runtime.h>
#include <cuda_fp16.h>
#include <math.h>
#include <stdint.h>

// ---------------------------------------------------------------------------
// SimpleCNN (DCLS) forward, B=4096.
// R4: conv2 via warp-level mma.sync (fp16 split-precision, 3 products),
// ldmatrix A-fragments, cp.async double-buffered weights.
// conv1 stays on packed fma.rn.f32x2; FC layers unchanged.
// ---------------------------------------------------------------------------

#define B_MAX 4096

__device__ float g_K1[32 * 36];              // (32,1) filters as 6x6 grids
__device__ float g_K2[64 * 32 * 36];         // (64,32) filters as 6x6 grids
__device__ float2 g_W1p[25 * 16];            // conv1 packed oc-pairs
__device__ __half g_W2t[25 * 2 * 64 * 32];   // [tap][h(hi/lo)][oc][ic]
__device__ float g_h1[B_MAX * 32 * 14 * 14];
__device__ float g_h2[B_MAX * 64 * 7 * 7];
__device__ float g_fc1[B_MAX * 128];

// Packed dual-FMA (sm_103 FFMA2)
__device__ __forceinline__ void fma2(float2& d, const float2& a, const float2& b) {
    asm("fma.rn.f32x2 %0, %1, %2, %0;"
        : "+l"(reinterpret_cast<unsigned long long&>(d))
        : "l"(reinterpret_cast<const unsigned long long&>(a)),
          "l"(reinterpret_cast<const unsigned long long&>(b)));
}

__device__ __forceinline__ uint32_t smem_u32(const void* p) {
    uint32_t a;
    asm("{ .reg .u64 t; cvta.to.shared.u64 t, %1; cvt.u32.u64 %0, t; }" : "=r"(a) : "l"(p));
    return a;
}

__device__ __forceinline__ void ldmx4(uint32_t* r, uint32_t addr) {
    asm volatile("ldmatrix.sync.aligned.m8n8.x4.shared.b16 {%0,%1,%2,%3}, [%4];"
        : "=r"(r[0]), "=r"(r[1]), "=r"(r[2]), "=r"(r[3]) : "r"(addr));
}

__device__ __forceinline__ void mma16816(float* c, const uint32_t* a, const uint32_t* b) {
    asm volatile(
        "mma.sync.aligned.m16n8k16.row.col.f32.f16.f16.f32 "
        "{%0,%1,%2,%3}, {%4,%5,%6,%7}, {%8,%9}, {%0,%1,%2,%3};"
        : "+f"(c[0]), "+f"(c[1]), "+f"(c[2]), "+f"(c[3])
        : "r"(a[0]), "r"(a[1]), "r"(a[2]), "r"(a[3]), "r"(b[0]), "r"(b[1]));
}

__device__ __forceinline__ void cp_async4(uint32_t dst, const void* src) {
    asm volatile("cp.async.ca.shared.global [%0], [%1], 4;" :: "r"(dst), "l"(src));
}
#define CP_COMMIT() asm volatile("cp.async.commit_group;" ::: "memory")
#define CP_WAIT1()  asm volatile("cp.async.wait_group 1;" ::: "memory")
#define CP_WAIT0()  asm volatile("cp.async.wait_group 0;" ::: "memory")

// ---------------- DCLS kernel construction ---------------------------------

__global__ void zero_k() {
    int i = blockIdx.x * blockDim.x + threadIdx.x;
    if (i < 32 * 36) g_K1[i] = 0.f;
    if (i < 64 * 32 * 36) g_K2[i] = 0.f;
}

__device__ __forceinline__ void dcls_scatter(float* grid, float w, float pa, float pb) {
    float p1c = fminf(fmaxf(pa, -2.f), 2.f) + 2.f;
    float p2c = fminf(fmaxf(pb, -2.f), 2.f) + 2.f;
    int i1 = (int)floorf(p1c);
    int i2 = (int)floorf(p2c);
    float r1 = p1c - (float)i1;
    float r2 = p2c - (float)i2;
    atomicAdd(&grid[i1 * 6 + i2],           w * (1.f - r1) * (1.f - r2));
    atomicAdd(&grid[(i1 + 1) * 6 + i2],     w * r1 * (1.f - r2));
    atomicAdd(&grid[i1 * 6 + i2 + 1],       w * (1.f - r1) * r2);
    atomicAdd(&grid[(i1 + 1) * 6 + i2 + 1], w * r1 * r2);
}

__global__ void build_k(const float* __restrict__ w1, const float* __restrict__ p1,
                        const float* __restrict__ w2, const float* __restrict__ p2) {
    int idx = blockIdx.x * blockDim.x + threadIdx.x;
    if (idx < 512) {
        float w = w1[idx];
        int f = idx / 16;
        dcls_scatter(g_K1 + f * 36, w, p1[idx], p1[512 + idx]);
    } else if (idx < 512 + 65536) {
        int e = idx - 512;
        float w = w2[e];
        int f = e / 32;
        dcls_scatter(g_K2 + f * 36, w, p2[e], p2[65536 + e]);
    }
}

__global__ void repack_k() {
    int i = blockIdx.x * blockDim.x + threadIdx.x;
    if (i < 400) {                          // conv1 packed pairs
        int t = i / 16, p = i % 16;
        int tap = (t / 5) * 6 + (t % 5);
        g_W1p[i] = make_float2(g_K1[(2 * p) * 36 + tap], g_K1[(2 * p + 1) * 36 + tap]);
    }
    if (i < 102400) {                       // conv2 fp16 hi/lo [tap][h][oc][ic]
        int t = i / 4096, r = i % 4096;
        int h = r >> 11, oc = (r >> 5) & 63, ic = r & 31;
        float w = g_K2[(oc * 32 + ic) * 36 + (t / 5) * 6 + (t % 5)];
        __half hi = __float2half(w);
        __half lo = __float2half(w - __half2float(hi));
        g_W2t[i] = h ? lo : hi;
    }
}

// ---------------- conv1 (unchanged from R2) --------------------------------

__global__ __launch_bounds__(448, 1) void conv1_kernel(const float* __restrict__ x,
                                                       const float* __restrict__ b1) {
    __shared__ float sIn[32 * 32];
    __shared__ float2 sW[25 * 16];
    int tid = threadIdx.x;
    int b = blockIdx.x;

    for (int i = tid; i < 1024; i += 448) sIn[i] = 0.f;
    if (tid < 400) sW[tid] = g_W1p[tid];
    __syncthreads();
    const float* xi = x + b * 784;
    for (int i = tid; i < 784; i += 448) {
        int y = i / 28, c = i % 28;
        sIn[(y + 2) * 32 + c + 2] = xi[i];
    }
    __syncthreads();

    int pair = tid & 15;
    int py = (tid >> 4) % 14;
    int xh = tid / 224;
    int Y = 2 * py, X0 = xh * 14;

    float2 acc[2][14];
#pragma unroll
    for (int r = 0; r < 2; r++)
#pragma unroll
        for (int c = 0; c < 14; c++) acc[r][c] = make_float2(0.f, 0.f);

#pragma unroll
    for (int dyy = 0; dyy < 6; dyy++) {
        const float* rp = sIn + (Y + dyy) * 32 + X0;
        float2 vp[18];
#pragma unroll
        for (int i = 0; i < 18; i++) { float v = rp[i]; vp[i] = make_float2(v, v); }
        if (dyy < 5) {
#pragma unroll
            for (int dx = 0; dx < 5; dx++) {
                float2 w = sW[(dyy * 5 + dx) * 16 + pair];
#pragma unroll
                for (int c = 0; c < 14; c++) fma2(acc[0][c], vp[c + dx], w);
            }
        }
        if (dyy >= 1) {
#pragma unroll
            for (int dx = 0; dx < 5; dx++) {
                float2 w = sW[((dyy - 1) * 5 + dx) * 16 + pair];
#pragma unroll
                for (int c = 0; c < 14; c++) fma2(acc[1][c], vp[c + dx], w);
            }
        }
    }

    int oc0 = 2 * pair;
    float blo = b1[oc0], bhi = b1[oc0 + 1];
    float* o0 = g_h1 + b * 6272 + oc0 * 196 + py * 14 + xh * 7;
    float* o1 = o0 + 196;
#pragma unroll
    for (int px = 0; px < 7; px++) {
        float2 q0 = acc[0][2 * px], q1 = acc[0][2 * px + 1];
        float2 q2 = acc[1][2 * px], q3 = acc[1][2 * px + 1];
        float mlo = fmaxf(fmaxf(q0.x, q1.x), fmaxf(q2.x, q3.x)) + blo;
        float mhi = fmaxf(fmaxf(q0.y, q1.y), fmaxf(q2.y, q3.y)) + bhi;
        o0[px] = fmaxf(mlo, 0.f);
        o1[px] = fmaxf(mhi, 0.f);
    }
}

// ---------------- conv2 via mma.sync ---------------------------------------
// CTA = 1 image, 224 thr (7 warps). X in SMEM: 324 padded-grid rows x 160B
// (32 ic fp16 hi at +0, lo at +80). Warp w owns m-tiles 2w, 2w+1 (16 sites
// each, 196 valid of 224). 25 taps x 2 kchunks x 3 split-products, N=64.

#define ROWB   160
#define XBYTES (324 * ROWB)                  // 51840
#define WTAP   9216                          // [h2][oc64][36 halves] * 2B
#define C2_SMEM (XBYTES + 2 * WTAP)          // 70272

__global__ __launch_bounds__(224, 2) void conv2_mma(const float* __restrict__ b2) {
    extern __shared__ __align__(16) char dsm[];
    uint32_t Xu = smem_u32(dsm);
    uint32_t Wu = Xu + XBYTES;

    int tid = threadIdx.x;
    int w = tid >> 5, l = tid & 31;
    int b = blockIdx.x;

    // ---- zero + fill X (fp16 hi/lo split, padded 18x18 grid) ----
    for (int i = tid; i < XBYTES / 16; i += 224)
        ((uint4*)dsm)[i] = make_uint4(0u, 0u, 0u, 0u);
    __syncthreads();
    const float* h1b = g_h1 + (size_t)b * 6272;
    for (int i = tid; i < 6272; i += 224) {
        int ic = i / 196, s = i % 196;
        int y = s / 14, x = s % 14;
        float v = h1b[i];
        __half hi = __float2half(v);
        __half lo = __float2half(v - __half2float(hi));
        int g = (y + 2) * 18 + (x + 2);
        *(__half*)(dsm + g * ROWB + 2 * ic) = hi;
        *(__half*)(dsm + g * ROWB + 80 + 2 * ic) = lo;
    }

    // ---- per-lane A addresses ----
    int row = l & 15, kh = l >> 4;
    uint32_t aBase[2];
#pragma unroll
    for (int mi = 0; mi < 2; mi++) {
        int s = (2 * w + mi) * 16 + row;
        if (s > 195) s = 0;
        int g0 = (s / 14) * 18 + (s % 14);
        aBase[mi] = Xu + (uint32_t)g0 * ROWB + (uint32_t)kh * 16;
    }
    // per-lane B address pieces: oc = n*8 + l/4, word = (h*64+oc)*18 + kc*8 + (l&3)
    uint32_t bOff = (uint32_t)((l >> 2) * 18 + (l & 3)) * 4;

    float acc[2][8][4];
#pragma unroll
    for (int mi = 0; mi < 2; mi++)
#pragma unroll
        for (int n = 0; n < 8; n++)
#pragma unroll
            for (int k = 0; k < 4; k++) acc[mi][n][k] = 0.f;

    // ---- stage tap 0 ----
    {
        const uint32_t* src = (const uint32_t*)g_W2t;
        for (int j = tid; j < 2048; j += 224) {
            int h = j >> 10, oc = (j >> 4) & 63, kp = j & 15;
            cp_async4(Wu + (uint32_t)(((h * 64 + oc) * 18 + kp) * 4), src + j);
        }
        CP_COMMIT();
    }

    // ---- main tap loop ----
    for (int t = 0; t < 25; t++) {
        if (t < 24) {
            const uint32_t* src = (const uint32_t*)(g_W2t + (t + 1) * 4096);
            uint32_t wdst = Wu + ((t + 1) & 1) * WTAP;
            for (int j = tid; j < 2048; j += 224) {
                int h = j >> 10, oc = (j >> 4) & 63, kp = j & 15;
                cp_async4(wdst + (uint32_t)(((h * 64 + oc) * 18 + kp) * 4), src + j);
            }
            CP_COMMIT();
            CP_WAIT1();
        } else {
            CP_WAIT0();
        }
        __syncthreads();

        uint32_t wb = Wu + (t & 1) * WTAP;
        uint32_t doff = (uint32_t)((t / 5) * 18 + (t % 5)) * ROWB;

#pragma unroll
        for (int kc = 0; kc < 2; kc++) {
            uint32_t ah[2][4], al[2][4];
            ldmx4(ah[0], aBase[0] + doff + kc * 32);
            ldmx4(ah[1], aBase[1] + doff + kc * 32);
            ldmx4(al[0], aBase[0] + 80 + doff + kc * 32);
            ldmx4(al[1], aBase[1] + 80 + doff + kc * 32);
            uint32_t bh_base = wb + bOff + (uint32_t)(kc * 32);
            uint32_t bl_base = bh_base + 64 * 18 * 4;
#pragma unroll
            for (int n0 = 0; n0 < 8; n0 += 2) {
                uint32_t bh[2][2], bl[2][2];
#pragma unroll
                for (int q = 0; q < 2; q++) {
                    uint32_t o = (uint32_t)(n0 + q) * 576;
                    bh[q][0] = *(const uint32_t*)(dsm + (bh_base + o - Xu));
                    bh[q][1] = *(const uint32_t*)(dsm + (bh_base + o + 16 - Xu));
                    bl[q][0] = *(const uint32_t*)(dsm + (bl_base + o - Xu));
                    bl[q][1] = *(const uint32_t*)(dsm + (bl_base + o + 16 - Xu));
                }
#pragma unroll
                for (int q = 0; q < 2; q++) {
#pragma unroll
                    for (int mi = 0; mi < 2; mi++) {
                        mma16816(acc[mi][n0 + q], ah[mi], bh[q]);
                        mma16816(acc[mi][n0 + q], ah[mi], bl[q]);
                        mma16816(acc[mi][n0 + q], al[mi], bh[q]);
                    }
                }
            }
        }
        __syncthreads();
    }

    // ---- epilogue: accums -> prepool SMEM -> pool+bias+relu -> g_h2 ----
    float* P = (float*)dsm;                  // [64 oc][198]
    int r = l >> 2, c2 = l & 3;
#pragma unroll
    for (int mi = 0; mi < 2; mi++) {
        int s0 = (2 * w + mi) * 16 + r;
        int s1 = s0 + 8;
#pragma unroll
        for (int n = 0; n < 8; n++) {
            int oc0 = n * 8 + 2 * c2;
            if (s0 < 196) {
                P[oc0 * 198 + s0] = acc[mi][n][0];
                P[(oc0 + 1) * 198 + s0] = acc[mi][n][1];
            }
            if (s1 < 196) {
                P[oc0 * 198 + s1] = acc[mi][n][2];
                P[(oc0 + 1) * 198 + s1] = acc[mi][n][3];
            }
        }
    }
    __syncthreads();
    for (int j = tid; j < 3136; j += 224) {
        int oc = j / 49, q = j % 49;
        int py = q / 7, px = q % 7;
        const float* pp = P + oc * 198 + (2 * py) * 14 + 2 * px;
        float v = fmaxf(fmaxf(pp[0], pp[1]), fmaxf(pp[14], pp[15]));
        g_h2[(size_t)b * 3136 + j] = fmaxf(v + b2[oc], 0.f);
    }
}

// ---------------- FC1: (B,3136) @ (128,3136)^T + bias, relu ----------------

__global__ void fc1_kernel(const float* __restrict__ W, const float* __restrict__ bias) {
    __shared__ float As[16][64];
    __shared__ float Bs[16][64];
    int tid = threadIdx.x;
    int tx = tid % 16, ty = tid / 16;
    int row0 = blockIdx.x * 64, col0 = blockIdx.y * 64;
    float acc[4][4] = {};
    int lm = tid / 4;
    int lk = (tid % 4) * 4;
    const float* Arow = g_h2 + (size_t)(row0 + lm) * 3136 + lk;
    const float* Brow = W + (size_t)(col0 + lm) * 3136 + lk;

    for (int kt = 0; kt < 3136; kt += 16) {
        float4 av = *(const float4*)(Arow + kt);
        float4 bv = *(const float4*)(Brow + kt);
        As[lk + 0][lm] = av.x; As[lk + 1][lm] = av.y;
        As[lk + 2][lm] = av.z; As[lk + 3][lm] = av.w;
        Bs[lk + 0][lm] = bv.x; Bs[lk + 1][lm] = bv.y;
        Bs[lk + 2][lm] = bv.z; Bs[lk + 3][lm] = bv.w;
        __syncthreads();
#pragma unroll
        for (int k = 0; k < 16; k++) {
            float ra[4], rb[4];
#pragma unroll
            for (int i = 0; i < 4; i++) { ra[i] = As[k][ty * 4 + i]; rb[i] = Bs[k][tx * 4 + i]; }
#pragma unroll
            for (int i = 0; i < 4; i++)
#pragma unroll
                for (int j = 0; j < 4; j++) acc[i][j] += ra[i] * rb[j];
        }
        __syncthreads();
    }
#pragma unroll
    for (int i = 0; i < 4; i++) {
        int rr = row0 + ty * 4 + i;
#pragma unroll
        for (int j = 0; j < 4; j++) {
            int c = col0 + tx * 4 + j;
            g_fc1[rr * 128 + c] = fmaxf(acc[i][j] + bias[c], 0.f);
        }
    }
}

// ---------------- FC2 ------------------------------------------------------

__global__ void fc2_kernel(const float* __restrict__ W, const float* __restrict__ bias,
                           float* __restrict__ out, int B) {
    int warp = (blockIdx.x * blockDim.x + threadIdx.x) / 32;
    int lane = threadIdx.x % 32;
    if (warp >= B) return;
    const float* hh = g_fc1 + warp * 128;
    float v0 = hh[lane], v1 = hh[32 + lane], v2 = hh[64 + lane], v3 = hh[96 + lane];
    float acc[10];
#pragma unroll
    for (int o = 0; o < 10; o++) {
        const float* ww = W + o * 128;
        float a = v0 * ww[lane] + v1 * ww[32 + lane] + v2 * ww[64 + lane] + v3 * ww[96 + lane];
#pragma unroll
        for (int off = 16; off > 0; off >>= 1)
            a += __shfl_xor_sync(0xFFFFFFFF, a, off);
        acc[o] = a;
    }
    if (lane == 0) {
#pragma unroll
        for (int o = 0; o < 10; o++) out[warp * 10 + o] = acc[o] + bias[o];
    }
}

// ---------------------------------------------------------------------------

extern "C" void kernel_launch(void* const* d_in, const int* in_sizes, int n_in,
                              void* d_out, int out_size) {
    const float* x    = (const float*)d_in[0];
    const float* w1   = (const float*)d_in[1];
    const float* p1   = (const float*)d_in[2];
    const float* b1   = (const float*)d_in[3];
    const float* w2   = (const float*)d_in[4];
    const float* p2   = (const float*)d_in[5];
    const float* b2   = (const float*)d_in[6];
    const float* fc1w = (const float*)d_in[7];
    const float* fc1b = (const float*)d_in[8];
    const float* fc2w = (const float*)d_in[9];
    const float* fc2b = (const float*)d_in[10];
    float* out = (float*)d_out;

    int B = in_sizes[0] / 784;
    if (B > B_MAX) B = B_MAX;

    zero_k<<<(64 * 32 * 36 + 255) / 256, 256>>>();
    build_k<<<(512 + 65536 + 255) / 256, 256>>>(w1, p1, w2, p2);
    repack_k<<<(102400 + 255) / 256, 256>>>();

    conv1_kernel<<<B, 448>>>(x, b1);

    cudaFuncSetAttribute(conv2_mma, cudaFuncAttributeMaxDynamicSharedMemorySize, C2_SMEM);
    conv2_mma<<<B, 224, C2_SMEM>>>(b2);

    dim3 g1(B / 64, 2);
    fc1_kernel<<<g1, 256>>>(fc1w, fc1b);
    fc2_kernel<<<(B * 32 + 255) / 256, 256>>>(fc2w, fc2b, out, B);
}

// round 5
// speedup vs baseline: 3.2468x; 1.1083x over previous
#include <cuda_runtime.h>
#include <cuda_fp16.h>
#include <math.h>
#include <stdint.h>

// ---------------------------------------------------------------------------
// SimpleCNN (DCLS) forward, B=4096.
// R5: conv2 mma warp-tile M=64 (4 warps, 3-buffer cp.async, 1 sync/tap);
// FC1 converted to split-fp16 mma.sync. conv1 FFMA2, FC2 unchanged.
// ---------------------------------------------------------------------------

#define B_MAX 4096

__device__ float g_K1[32 * 36];
__device__ float g_K2[64 * 32 * 36];
__device__ float2 g_W1p[25 * 16];
__device__ __half g_W2t[25 * 2 * 64 * 32];       // [tap][h][oc][ic]
__device__ float g_h1[B_MAX * 32 * 14 * 14];
__device__ __half g_h2h[(size_t)B_MAX * 3136];   // conv2 out hi
__device__ __half g_h2l[(size_t)B_MAX * 3136];   // conv2 out lo
__device__ __half g_F1h[128 * 3136];             // fc1 weights hi
__device__ __half g_F1l[128 * 3136];             // fc1 weights lo
__device__ float g_fc1[B_MAX * 128];

__device__ __forceinline__ void fma2(float2& d, const float2& a, const float2& b) {
    asm("fma.rn.f32x2 %0, %1, %2, %0;"
        : "+l"(reinterpret_cast<unsigned long long&>(d))
        : "l"(reinterpret_cast<const unsigned long long&>(a)),
          "l"(reinterpret_cast<const unsigned long long&>(b)));
}

__device__ __forceinline__ uint32_t smem_u32(const void* p) {
    uint32_t a;
    asm("{ .reg .u64 t; cvta.to.shared.u64 t, %1; cvt.u32.u64 %0, t; }" : "=r"(a) : "l"(p));
    return a;
}

__device__ __forceinline__ void ldmx4(uint32_t* r, uint32_t addr) {
    asm volatile("ldmatrix.sync.aligned.m8n8.x4.shared.b16 {%0,%1,%2,%3}, [%4];"
        : "=r"(r[0]), "=r"(r[1]), "=r"(r[2]), "=r"(r[3]) : "r"(addr));
}

__device__ __forceinline__ void mma16816(float* c, const uint32_t* a, const uint32_t* b) {
    asm volatile(
        "mma.sync.aligned.m16n8k16.row.col.f32.f16.f16.f32 "
        "{%0,%1,%2,%3}, {%4,%5,%6,%7}, {%8,%9}, {%0,%1,%2,%3};"
        : "+f"(c[0]), "+f"(c[1]), "+f"(c[2]), "+f"(c[3])
        : "r"(a[0]), "r"(a[1]), "r"(a[2]), "r"(a[3]), "r"(b[0]), "r"(b[1]));
}

__device__ __forceinline__ void cp_async4(uint32_t dst, const void* src) {
    asm volatile("cp.async.ca.shared.global [%0], [%1], 4;" :: "r"(dst), "l"(src));
}
__device__ __forceinline__ void cp_async16(uint32_t dst, const void* src) {
    asm volatile("cp.async.ca.shared.global [%0], [%1], 16;" :: "r"(dst), "l"(src));
}
#define CP_COMMIT() asm volatile("cp.async.commit_group;" ::: "memory")
#define CP_WAIT1()  asm volatile("cp.async.wait_group 1;" ::: "memory")
#define CP_WAIT0()  asm volatile("cp.async.wait_group 0;" ::: "memory")

// ---------------- DCLS kernel construction ---------------------------------

__global__ void zero_k() {
    int i = blockIdx.x * blockDim.x + threadIdx.x;
    if (i < 32 * 36) g_K1[i] = 0.f;
    if (i < 64 * 32 * 36) g_K2[i] = 0.f;
}

__device__ __forceinline__ void dcls_scatter(float* grid, float w, float pa, float pb) {
    float p1c = fminf(fmaxf(pa, -2.f), 2.f) + 2.f;
    float p2c = fminf(fmaxf(pb, -2.f), 2.f) + 2.f;
    int i1 = (int)floorf(p1c);
    int i2 = (int)floorf(p2c);
    float r1 = p1c - (float)i1;
    float r2 = p2c - (float)i2;
    atomicAdd(&grid[i1 * 6 + i2],           w * (1.f - r1) * (1.f - r2));
    atomicAdd(&grid[(i1 + 1) * 6 + i2],     w * r1 * (1.f - r2));
    atomicAdd(&grid[i1 * 6 + i2 + 1],       w * (1.f - r1) * r2);
    atomicAdd(&grid[(i1 + 1) * 6 + i2 + 1], w * r1 * r2);
}

__global__ void build_k(const float* __restrict__ w1, const float* __restrict__ p1,
                        const float* __restrict__ w2, const float* __restrict__ p2) {
    int idx = blockIdx.x * blockDim.x + threadIdx.x;
    if (idx < 512) {
        float w = w1[idx];
        int f = idx / 16;
        dcls_scatter(g_K1 + f * 36, w, p1[idx], p1[512 + idx]);
    } else if (idx < 512 + 65536) {
        int e = idx - 512;
        float w = w2[e];
        int f = e / 32;
        dcls_scatter(g_K2 + f * 36, w, p2[e], p2[65536 + e]);
    }
}

__global__ void repack_k() {
    int i = blockIdx.x * blockDim.x + threadIdx.x;
    if (i < 400) {
        int t = i / 16, p = i % 16;
        int tap = (t / 5) * 6 + (t % 5);
        g_W1p[i] = make_float2(g_K1[(2 * p) * 36 + tap], g_K1[(2 * p + 1) * 36 + tap]);
    }
    if (i < 102400) {
        int t = i / 4096, r = i % 4096;
        int h = r >> 11, oc = (r >> 5) & 63, ic = r & 31;
        float w = g_K2[(oc * 32 + ic) * 36 + (t / 5) * 6 + (t % 5)];
        __half hi = __float2half(w);
        __half lo = __float2half(w - __half2float(hi));
        g_W2t[i] = h ? lo : hi;
    }
}

__global__ void repack_fc1(const float* __restrict__ W) {
    int i = blockIdx.x * blockDim.x + threadIdx.x;
    if (i < 128 * 3136) {
        float w = W[i];
        __half hi = __float2half(w);
        g_F1h[i] = hi;
        g_F1l[i] = __float2half(w - __half2float(hi));
    }
}

// ---------------- conv1 (unchanged) ----------------------------------------

__global__ __launch_bounds__(448, 1) void conv1_kernel(const float* __restrict__ x,
                                                       const float* __restrict__ b1) {
    __shared__ float sIn[32 * 32];
    __shared__ float2 sW[25 * 16];
    int tid = threadIdx.x;
    int b = blockIdx.x;

    for (int i = tid; i < 1024; i += 448) sIn[i] = 0.f;
    if (tid < 400) sW[tid] = g_W1p[tid];
    __syncthreads();
    const float* xi = x + b * 784;
    for (int i = tid; i < 784; i += 448) {
        int y = i / 28, c = i % 28;
        sIn[(y + 2) * 32 + c + 2] = xi[i];
    }
    __syncthreads();

    int pair = tid & 15;
    int py = (tid >> 4) % 14;
    int xh = tid / 224;
    int Y = 2 * py, X0 = xh * 14;

    float2 acc[2][14];
#pragma unroll
    for (int r = 0; r < 2; r++)
#pragma unroll
        for (int c = 0; c < 14; c++) acc[r][c] = make_float2(0.f, 0.f);

#pragma unroll
    for (int dyy = 0; dyy < 6; dyy++) {
        const float* rp = sIn + (Y + dyy) * 32 + X0;
        float2 vp[18];
#pragma unroll
        for (int i = 0; i < 18; i++) { float v = rp[i]; vp[i] = make_float2(v, v); }
        if (dyy < 5) {
#pragma unroll
            for (int dx = 0; dx < 5; dx++) {
                float2 w = sW[(dyy * 5 + dx) * 16 + pair];
#pragma unroll
                for (int c = 0; c < 14; c++) fma2(acc[0][c], vp[c + dx], w);
            }
        }
        if (dyy >= 1) {
#pragma unroll
            for (int dx = 0; dx < 5; dx++) {
                float2 w = sW[((dyy - 1) * 5 + dx) * 16 + pair];
#pragma unroll
                for (int c = 0; c < 14; c++) fma2(acc[1][c], vp[c + dx], w);
            }
        }
    }

    int oc0 = 2 * pair;
    float blo = b1[oc0], bhi = b1[oc0 + 1];
    float* o0 = g_h1 + b * 6272 + oc0 * 196 + py * 14 + xh * 7;
    float* o1 = o0 + 196;
#pragma unroll
    for (int px = 0; px < 7; px++) {
        float2 q0 = acc[0][2 * px], q1 = acc[0][2 * px + 1];
        float2 q2 = acc[1][2 * px], q3 = acc[1][2 * px + 1];
        float mlo = fmaxf(fmaxf(q0.x, q1.x), fmaxf(q2.x, q3.x)) + blo;
        float mhi = fmaxf(fmaxf(q0.y, q1.y), fmaxf(q2.y, q3.y)) + bhi;
        o0[px] = fmaxf(mlo, 0.f);
        o1[px] = fmaxf(mhi, 0.f);
    }
}

// ---------------- conv2 via mma.sync, warp tile M=64 -----------------------
// CTA = 1 image, 128 thr (4 warps x 4 m16-tiles). 25 taps, 3-buffer weights.

#define ROWB   160
#define XBYTES (324 * ROWB)                  // 51840
#define WTAP   9216
#define C2_SMEM (XBYTES + 3 * WTAP)          // 79488

__global__ __launch_bounds__(128, 2) void conv2_mma(const float* __restrict__ b2) {
    extern __shared__ __align__(16) char dsm[];
    uint32_t Xu = smem_u32(dsm);
    uint32_t Wu = Xu + XBYTES;

    int tid = threadIdx.x;
    int w = tid >> 5, l = tid & 31;
    int b = blockIdx.x;

    for (int i = tid; i < XBYTES / 16; i += 128)
        ((uint4*)dsm)[i] = make_uint4(0u, 0u, 0u, 0u);
    __syncthreads();
    const float* h1b = g_h1 + (size_t)b * 6272;
    for (int i = tid; i < 6272; i += 128) {
        int ic = i / 196, s = i % 196;
        int y = s / 14, x = s % 14;
        float v = h1b[i];
        __half hi = __float2half(v);
        __half lo = __float2half(v - __half2float(hi));
        int g = (y + 2) * 18 + (x + 2);
        *(__half*)(dsm + g * ROWB + 2 * ic) = hi;
        *(__half*)(dsm + g * ROWB + 80 + 2 * ic) = lo;
    }

    int row = l & 15, kh = l >> 4;
    uint32_t aBase[4];
#pragma unroll
    for (int mi = 0; mi < 4; mi++) {
        int s = (w * 4 + mi) * 16 + row;
        if (s > 195) s = 0;
        int g0 = (s / 14) * 18 + (s % 14);
        aBase[mi] = Xu + (uint32_t)g0 * ROWB + (uint32_t)kh * 16;
    }
    uint32_t bOff = (uint32_t)((l >> 2) * 18 + (l & 3)) * 4;

    float acc[4][8][4];
#pragma unroll
    for (int mi = 0; mi < 4; mi++)
#pragma unroll
        for (int n = 0; n < 8; n++)
#pragma unroll
            for (int k = 0; k < 4; k++) acc[mi][n][k] = 0.f;

    // stage tap 0 into buf 0
    {
        const uint32_t* src = (const uint32_t*)g_W2t;
        for (int j = tid; j < 2048; j += 128) {
            int h = j >> 10, oc = (j >> 4) & 63, kp = j & 15;
            cp_async4(Wu + (uint32_t)(((h * 64 + oc) * 18 + kp) * 4), src + j);
        }
        CP_COMMIT();
    }

    for (int t = 0; t < 25; t++) {
        if (t < 24) {
            const uint32_t* src = (const uint32_t*)(g_W2t + (t + 1) * 4096);
            uint32_t wdst = Wu + (uint32_t)(((t + 1) % 3) * WTAP);
            for (int j = tid; j < 2048; j += 128) {
                int h = j >> 10, oc = (j >> 4) & 63, kp = j & 15;
                cp_async4(wdst + (uint32_t)(((h * 64 + oc) * 18 + kp) * 4), src + j);
            }
            CP_COMMIT();
            CP_WAIT1();
        } else {
            CP_WAIT0();
        }
        __syncthreads();

        uint32_t wb = Wu + (uint32_t)((t % 3) * WTAP);
        uint32_t doff = (uint32_t)((t / 5) * 18 + (t % 5)) * ROWB;

#pragma unroll
        for (int kc = 0; kc < 2; kc++) {
            uint32_t ah[4][4], al[4][4];
#pragma unroll
            for (int mi = 0; mi < 4; mi++) {
                ldmx4(ah[mi], aBase[mi] + doff + kc * 32);
                ldmx4(al[mi], aBase[mi] + 80 + doff + kc * 32);
            }
            uint32_t bh_base = wb + bOff + (uint32_t)(kc * 32);
#pragma unroll
            for (int n = 0; n < 8; n++) {
                uint32_t o = (uint32_t)n * 576;
                uint32_t bh[2], bl[2];
                bh[0] = *(const uint32_t*)(dsm + (bh_base + o - Xu));
                bh[1] = *(const uint32_t*)(dsm + (bh_base + o + 16 - Xu));
                bl[0] = *(const uint32_t*)(dsm + (bh_base + o + 4608 - Xu));
                bl[1] = *(const uint32_t*)(dsm + (bh_base + o + 4624 - Xu));
#pragma unroll
                for (int mi = 0; mi < 4; mi++) {
                    mma16816(acc[mi][n], ah[mi], bh);
                    mma16816(acc[mi][n], ah[mi], bl);
                    mma16816(acc[mi][n], al[mi], bh);
                }
            }
        }
    }
    __syncthreads();

    // epilogue: acc -> prepool P -> pool+bias+relu -> fp16 hi/lo h2
    float* P = (float*)dsm;                  // [64 oc][198]
    int r = l >> 2, c2 = l & 3;
#pragma unroll
    for (int mi = 0; mi < 4; mi++) {
        int s0 = (w * 4 + mi) * 16 + r;
        int s1 = s0 + 8;
#pragma unroll
        for (int n = 0; n < 8; n++) {
            int oc0 = n * 8 + 2 * c2;
            if (s0 < 196) {
                P[oc0 * 198 + s0] = acc[mi][n][0];
                P[(oc0 + 1) * 198 + s0] = acc[mi][n][1];
            }
            if (s1 < 196) {
                P[oc0 * 198 + s1] = acc[mi][n][2];
                P[(oc0 + 1) * 198 + s1] = acc[mi][n][3];
            }
        }
    }
    __syncthreads();
    for (int j = tid; j < 3136; j += 128) {
        int oc = j / 49, q = j % 49;
        int py = q / 7, px = q % 7;
        const float* pp = P + oc * 198 + (2 * py) * 14 + 2 * px;
        float v = fmaxf(fmaxf(pp[0], pp[1]), fmaxf(pp[14], pp[15]));
        v = fmaxf(v + b2[oc], 0.f);
        __half hi = __float2half(v);
        g_h2h[(size_t)b * 3136 + j] = hi;
        g_h2l[(size_t)b * 3136 + j] = __float2half(v - __half2float(hi));
    }
}

// ---------------- FC1 via mma.sync -----------------------------------------
// C[4096,128] = h2 @ W^T. CTA tile 64x64, 4 warps (2m x 2n), warp 32x32.
// K = 3136 = 196 k16 steps, 3-buffer cp.async, split-fp16 3 products.

#define F1ROWB 80
#define F1BUF  (128 * F1ROWB)                // 10240
#define FC1_SMEM (3 * F1BUF)

__global__ __launch_bounds__(128, 4) void fc1_mma(const float* __restrict__ bias) {
    extern __shared__ __align__(16) char fsm[];
    uint32_t Su = smem_u32(fsm);

    int tid = threadIdx.x;
    int w = tid >> 5, l = tid & 31;
    int wm = w >> 1, wn = w & 1;
    int m0 = blockIdx.x * 64, n0 = blockIdx.y * 64;

    float acc[2][4][4];
#pragma unroll
    for (int mi = 0; mi < 2; mi++)
#pragma unroll
        for (int nt = 0; nt < 4; nt++)
#pragma unroll
            for (int k = 0; k < 4; k++) acc[mi][nt][k] = 0.f;

    // staging: 512 16B chunks per kstep; thread does 4
    // c: row = c>>2 (0..63 A img rows, 64..127 B oc rows), part = c&3
    auto stage = [&](int kt, int buf) {
        uint32_t dst0 = Su + (uint32_t)(buf * F1BUF);
        int k0 = kt * 16;
#pragma unroll
        for (int i = 0; i < 4; i++) {
            int c = tid + 128 * i;
            int rrow = c >> 2, part = c & 3;
            const __half* src;
            if (rrow < 64) {
                const __half* base = (part >= 2) ? g_h2l : g_h2h;
                src = base + (size_t)(m0 + rrow) * 3136 + k0 + (part & 1) * 8;
            } else {
                const __half* base = (part >= 2) ? g_F1l : g_F1h;
                src = base + (size_t)(n0 + rrow - 64) * 3136 + k0 + (part & 1) * 8;
            }
            uint32_t dst = dst0 + (uint32_t)(rrow * F1ROWB)
                         + (uint32_t)((part & 2) * 16 + (part & 1) * 16);
            cp_async16(dst, src);
        }
        CP_COMMIT();
    };

    stage(0, 0);

    // per-lane addresses
    int arow = l & 15, ach = l >> 4;
    uint32_t aAddr[2];
#pragma unroll
    for (int mi = 0; mi < 2; mi++)
        aAddr[mi] = Su + (uint32_t)(((wm * 2 + mi) * 16 + arow) * F1ROWB + ach * 16);
    uint32_t bRow0 = (uint32_t)(64 + wn * 32 + (l >> 2));
    uint32_t bW0 = (uint32_t)((l & 3) * 4);

    for (int kt = 0; kt < 196; kt++) {
        if (kt < 195) { stage(kt + 1, (kt + 1) % 3); CP_WAIT1(); }
        else CP_WAIT0();
        __syncthreads();
        uint32_t bufo = (uint32_t)((kt % 3) * F1BUF);

        uint32_t ah[2][4], al[2][4];
#pragma unroll
        for (int mi = 0; mi < 2; mi++) {
            ldmx4(ah[mi], aAddr[mi] + bufo);
            ldmx4(al[mi], aAddr[mi] + bufo + 32);
        }
#pragma unroll
        for (int nt = 0; nt < 4; nt++) {
            uint32_t rb = bufo + (bRow0 + nt * 8) * F1ROWB + bW0;
            uint32_t bh[2], bl[2];
            bh[0] = *(const uint32_t*)(fsm + rb);
            bh[1] = *(const uint32_t*)(fsm + rb + 16);
            bl[0] = *(const uint32_t*)(fsm + rb + 32);
            bl[1] = *(const uint32_t*)(fsm + rb + 48);
#pragma unroll
            for (int mi = 0; mi < 2; mi++) {
                mma16816(acc[mi][nt], ah[mi], bh);
                mma16816(acc[mi][nt], ah[mi], bl);
                mma16816(acc[mi][nt], al[mi], bh);
            }
        }
        __syncthreads();
    }

    // epilogue
#pragma unroll
    for (int mi = 0; mi < 2; mi++) {
        int mr0 = m0 + wm * 32 + mi * 16 + (l >> 2);
#pragma unroll
        for (int nt = 0; nt < 4; nt++) {
            int col = n0 + wn * 32 + nt * 8 + 2 * (l & 3);
            float bsv0 = bias[col], bsv1 = bias[col + 1];
            g_fc1[mr0 * 128 + col]     = fmaxf(acc[mi][nt][0] + bsv0, 0.f);
            g_fc1[mr0 * 128 + col + 1] = fmaxf(acc[mi][nt][1] + bsv1, 0.f);
            g_fc1[(mr0 + 8) * 128 + col]     = fmaxf(acc[mi][nt][2] + bsv0, 0.f);
            g_fc1[(mr0 + 8) * 128 + col + 1] = fmaxf(acc[mi][nt][3] + bsv1, 0.f);
        }
    }
}

// ---------------- FC2 ------------------------------------------------------

__global__ void fc2_kernel(const float* __restrict__ W, const float* __restrict__ bias,
                           float* __restrict__ out, int B) {
    int warp = (blockIdx.x * blockDim.x + threadIdx.x) / 32;
    int lane = threadIdx.x % 32;
    if (warp >= B) return;
    const float* hh = g_fc1 + warp * 128;
    float v0 = hh[lane], v1 = hh[32 + lane], v2 = hh[64 + lane], v3 = hh[96 + lane];
    float acc[10];
#pragma unroll
    for (int o = 0; o < 10; o++) {
        const float* ww = W + o * 128;
        float a = v0 * ww[lane] + v1 * ww[32 + lane] + v2 * ww[64 + lane] + v3 * ww[96 + lane];
#pragma unroll
        for (int off = 16; off > 0; off >>= 1)
            a += __shfl_xor_sync(0xFFFFFFFF, a, off);
        acc[o] = a;
    }
    if (lane == 0) {
#pragma unroll
        for (int o = 0; o < 10; o++) out[warp * 10 + o] = acc[o] + bias[o];
    }
}

// ---------------------------------------------------------------------------

extern "C" void kernel_launch(void* const* d_in, const int* in_sizes, int n_in,
                              void* d_out, int out_size) {
    const float* x    = (const float*)d_in[0];
    const float* w1   = (const float*)d_in[1];
    const float* p1   = (const float*)d_in[2];
    const float* b1   = (const float*)d_in[3];
    const float* w2   = (const float*)d_in[4];
    const float* p2   = (const float*)d_in[5];
    const float* b2   = (const float*)d_in[6];
    const float* fc1w = (const float*)d_in[7];
    const float* fc1b = (const float*)d_in[8];
    const float* fc2w = (const float*)d_in[9];
    const float* fc2b = (const float*)d_in[10];
    float* out = (float*)d_out;

    int B = in_sizes[0] / 784;
    if (B > B_MAX) B = B_MAX;

    zero_k<<<(64 * 32 * 36 + 255) / 256, 256>>>();
    build_k<<<(512 + 65536 + 255) / 256, 256>>>(w1, p1, w2, p2);
    repack_k<<<(102400 + 255) / 256, 256>>>();
    repack_fc1<<<(128 * 3136 + 255) / 256, 256>>>(fc1w);

    conv1_kernel<<<B, 448>>>(x, b1);

    cudaFuncSetAttribute(conv2_mma, cudaFuncAttributeMaxDynamicSharedMemorySize, C2_SMEM);
    conv2_mma<<<B, 128, C2_SMEM>>>(b2);

    cudaFuncSetAttribute(fc1_mma, cudaFuncAttributeMaxDynamicSharedMemorySize, FC1_SMEM);
    dim3 gf(B / 64, 2);
    fc1_mma<<<gf, 128, FC1_SMEM>>>(fc1b);

    fc2_kernel<<<(B * 32 + 255) / 256, 256>>>(fc2w, fc2b, out, B);
}

// round 6
// speedup vs baseline: 4.4107x; 1.3585x over previous
#include <cuda_runtime.h>
#include <cuda_fp16.h>
#include <math.h>
#include <stdint.h>

// ---------------------------------------------------------------------------
// SimpleCNN (DCLS) forward, B=4096.
// R6: h1 stored as fp16 -> conv2 uses 2-product split (A exact fp16, B hi/lo);
// FC1 full-width N=128 with fused FC2 epilogue (fc2 kernel + g_fc1 removed).
// ---------------------------------------------------------------------------

#define B_MAX 4096

__device__ float g_K1[32 * 36];
__device__ float g_K2[64 * 32 * 36];
__device__ float2 g_W1p[25 * 16];
__device__ __half g_W2t[25 * 2 * 64 * 32];       // [tap][h][oc][ic]
__device__ __half g_h1h[(size_t)B_MAX * 6272];   // conv1 out, fp16
__device__ __half g_h2h[(size_t)B_MAX * 3136];   // conv2 out hi
__device__ __half g_h2l[(size_t)B_MAX * 3136];   // conv2 out lo
__device__ __half g_F1h[128 * 3136];             // fc1 weights hi
__device__ __half g_F1l[128 * 3136];             // fc1 weights lo

__device__ __forceinline__ void fma2(float2& d, const float2& a, const float2& b) {
    asm("fma.rn.f32x2 %0, %1, %2, %0;"
        : "+l"(reinterpret_cast<unsigned long long&>(d))
        : "l"(reinterpret_cast<const unsigned long long&>(a)),
          "l"(reinterpret_cast<const unsigned long long&>(b)));
}

__device__ __forceinline__ uint32_t smem_u32(const void* p) {
    uint32_t a;
    asm("{ .reg .u64 t; cvta.to.shared.u64 t, %1; cvt.u32.u64 %0, t; }" : "=r"(a) : "l"(p));
    return a;
}

__device__ __forceinline__ void ldmx4(uint32_t* r, uint32_t addr) {
    asm volatile("ldmatrix.sync.aligned.m8n8.x4.shared.b16 {%0,%1,%2,%3}, [%4];"
        : "=r"(r[0]), "=r"(r[1]), "=r"(r[2]), "=r"(r[3]) : "r"(addr));
}

__device__ __forceinline__ void mma16816(float* c, const uint32_t* a, const uint32_t* b) {
    asm volatile(
        "mma.sync.aligned.m16n8k16.row.col.f32.f16.f16.f32 "
        "{%0,%1,%2,%3}, {%4,%5,%6,%7}, {%8,%9}, {%0,%1,%2,%3};"
        : "+f"(c[0]), "+f"(c[1]), "+f"(c[2]), "+f"(c[3])
        : "r"(a[0]), "r"(a[1]), "r"(a[2]), "r"(a[3]), "r"(b[0]), "r"(b[1]));
}

__device__ __forceinline__ void cp_async16(uint32_t dst, const void* src) {
    asm volatile("cp.async.ca.shared.global [%0], [%1], 16;" :: "r"(dst), "l"(src));
}
#define CP_COMMIT() asm volatile("cp.async.commit_group;" ::: "memory")
#define CP_WAIT1()  asm volatile("cp.async.wait_group 1;" ::: "memory")
#define CP_WAIT0()  asm volatile("cp.async.wait_group 0;" ::: "memory")

// ---------------- DCLS kernel construction ---------------------------------

__global__ void zero_k() {
    int i = blockIdx.x * blockDim.x + threadIdx.x;
    if (i < 32 * 36) g_K1[i] = 0.f;
    if (i < 64 * 32 * 36) g_K2[i] = 0.f;
}

__device__ __forceinline__ void dcls_scatter(float* grid, float w, float pa, float pb) {
    float p1c = fminf(fmaxf(pa, -2.f), 2.f) + 2.f;
    float p2c = fminf(fmaxf(pb, -2.f), 2.f) + 2.f;
    int i1 = (int)floorf(p1c);
    int i2 = (int)floorf(p2c);
    float r1 = p1c - (float)i1;
    float r2 = p2c - (float)i2;
    atomicAdd(&grid[i1 * 6 + i2],           w * (1.f - r1) * (1.f - r2));
    atomicAdd(&grid[(i1 + 1) * 6 + i2],     w * r1 * (1.f - r2));
    atomicAdd(&grid[i1 * 6 + i2 + 1],       w * (1.f - r1) * r2);
    atomicAdd(&grid[(i1 + 1) * 6 + i2 + 1], w * r1 * r2);
}

__global__ void build_k(const float* __restrict__ w1, const float* __restrict__ p1,
                        const float* __restrict__ w2, const float* __restrict__ p2) {
    int idx = blockIdx.x * blockDim.x + threadIdx.x;
    if (idx < 512) {
        float w = w1[idx];
        int f = idx / 16;
        dcls_scatter(g_K1 + f * 36, w, p1[idx], p1[512 + idx]);
    } else if (idx < 512 + 65536) {
        int e = idx - 512;
        float w = w2[e];
        int f = e / 32;
        dcls_scatter(g_K2 + f * 36, w, p2[e], p2[65536 + e]);
    }
}

__global__ void repack_k() {
    int i = blockIdx.x * blockDim.x + threadIdx.x;
    if (i < 400) {
        int t = i / 16, p = i % 16;
        int tap = (t / 5) * 6 + (t % 5);
        g_W1p[i] = make_float2(g_K1[(2 * p) * 36 + tap], g_K1[(2 * p + 1) * 36 + tap]);
    }
    if (i < 102400) {
        int t = i / 4096, r = i % 4096;
        int h = r >> 11, oc = (r >> 5) & 63, ic = r & 31;
        float w = g_K2[(oc * 32 + ic) * 36 + (t / 5) * 6 + (t % 5)];
        __half hi = __float2half(w);
        __half lo = __float2half(w - __half2float(hi));
        g_W2t[i] = h ? lo : hi;
    }
}

__global__ void repack_fc1(const float* __restrict__ W) {
    int i = blockIdx.x * blockDim.x + threadIdx.x;
    if (i < 128 * 3136) {
        float w = W[i];
        __half hi = __float2half(w);
        g_F1h[i] = hi;
        g_F1l[i] = __float2half(w - __half2float(hi));
    }
}

// ---------------- conv1 (FFMA2, epilogue -> fp16) --------------------------

__global__ __launch_bounds__(448, 1) void conv1_kernel(const float* __restrict__ x,
                                                       const float* __restrict__ b1) {
    __shared__ float sIn[32 * 32];
    __shared__ float2 sW[25 * 16];
    int tid = threadIdx.x;
    int b = blockIdx.x;

    for (int i = tid; i < 1024; i += 448) sIn[i] = 0.f;
    if (tid < 400) sW[tid] = g_W1p[tid];
    __syncthreads();
    const float* xi = x + b * 784;
    for (int i = tid; i < 784; i += 448) {
        int y = i / 28, c = i % 28;
        sIn[(y + 2) * 32 + c + 2] = xi[i];
    }
    __syncthreads();

    int pair = tid & 15;
    int py = (tid >> 4) % 14;
    int xh = tid / 224;
    int Y = 2 * py, X0 = xh * 14;

    float2 acc[2][14];
#pragma unroll
    for (int r = 0; r < 2; r++)
#pragma unroll
        for (int c = 0; c < 14; c++) acc[r][c] = make_float2(0.f, 0.f);

#pragma unroll
    for (int dyy = 0; dyy < 6; dyy++) {
        const float* rp = sIn + (Y + dyy) * 32 + X0;
        float2 vp[18];
#pragma unroll
        for (int i = 0; i < 18; i++) { float v = rp[i]; vp[i] = make_float2(v, v); }
        if (dyy < 5) {
#pragma unroll
            for (int dx = 0; dx < 5; dx++) {
                float2 w = sW[(dyy * 5 + dx) * 16 + pair];
#pragma unroll
                for (int c = 0; c < 14; c++) fma2(acc[0][c], vp[c + dx], w);
            }
        }
        if (dyy >= 1) {
#pragma unroll
            for (int dx = 0; dx < 5; dx++) {
                float2 w = sW[((dyy - 1) * 5 + dx) * 16 + pair];
#pragma unroll
                for (int c = 0; c < 14; c++) fma2(acc[1][c], vp[c + dx], w);
            }
        }
    }

    int oc0 = 2 * pair;
    float blo = b1[oc0], bhi = b1[oc0 + 1];
    __half* o0 = g_h1h + (size_t)b * 6272 + oc0 * 196 + py * 14 + xh * 7;
    __half* o1 = o0 + 196;
#pragma unroll
    for (int px = 0; px < 7; px++) {
        float2 q0 = acc[0][2 * px], q1 = acc[0][2 * px + 1];
        float2 q2 = acc[1][2 * px], q3 = acc[1][2 * px + 1];
        float mlo = fmaxf(fmaxf(q0.x, q1.x), fmaxf(q2.x, q3.x)) + blo;
        float mhi = fmaxf(fmaxf(q0.y, q1.y), fmaxf(q2.y, q3.y)) + bhi;
        o0[px] = __float2half(fmaxf(mlo, 0.f));
        o1[px] = __float2half(fmaxf(mhi, 0.f));
    }
}

// ---------------- conv2 via mma.sync, 2-product split ----------------------
// CTA = 1 image, 128 thr (4 warps x 4 m16 tiles). X rows: 324 grid pos x 80B
// (32 ic fp16, A exact). Weights hi/lo (128 rows x 80B), 3-buffer cp.async.

#define ROWB    80
#define XBYTES  (324 * ROWB)                 // 25920
#define WROWB   80
#define WTAP    (128 * WROWB)                // 10240
#define C2_SMEM (XBYTES + 3 * WTAP)          // 56640 (>= epilogue 64*198*4)

__global__ __launch_bounds__(128, 2) void conv2_mma(const float* __restrict__ b2) {
    extern __shared__ __align__(16) char dsm[];
    uint32_t Xu = smem_u32(dsm);
    uint32_t Wu = Xu + XBYTES;

    int tid = threadIdx.x;
    int w = tid >> 5, l = tid & 31;
    int b = blockIdx.x;

    for (int i = tid; i < XBYTES / 16; i += 128)
        ((uint4*)dsm)[i] = make_uint4(0u, 0u, 0u, 0u);
    __syncthreads();
    // fill X from fp16 h1 (u32 = 2 adjacent sites of one ic; rows of 14 even)
    const uint32_t* h1b = (const uint32_t*)(g_h1h + (size_t)b * 6272);
    for (int i = tid; i < 3136; i += 128) {
        uint32_t v = h1b[i];
        int ic = i / 98, p = i % 98;
        int s = 2 * p;
        int y = s / 14, x = s % 14;
        int g = (y + 2) * 18 + (x + 2);
        *(uint16_t*)(dsm + g * ROWB + 2 * ic) = (uint16_t)(v & 0xFFFF);
        *(uint16_t*)(dsm + (g + 1) * ROWB + 2 * ic) = (uint16_t)(v >> 16);
    }

    int row = l & 15, kh = l >> 4;
    uint32_t aBase[4];
#pragma unroll
    for (int mi = 0; mi < 4; mi++) {
        int s = (w * 4 + mi) * 16 + row;
        if (s > 195) s = 0;
        int g0 = (s / 14) * 18 + (s % 14);
        aBase[mi] = Xu + (uint32_t)g0 * ROWB + (uint32_t)kh * 16;
    }
    uint32_t bOff = (uint32_t)((l >> 2) * WROWB + (l & 3) * 4);

    float acc[4][8][4];
#pragma unroll
    for (int mi = 0; mi < 4; mi++)
#pragma unroll
        for (int n = 0; n < 8; n++)
#pragma unroll
            for (int k = 0; k < 4; k++) acc[mi][n][k] = 0.f;

    // stage tap 0 into buf 0 (rows: h*64+oc, 64B data per row, 4x16B chunks)
    {
        const char* src = (const char*)g_W2t;
#pragma unroll
        for (int i = 0; i < 4; i++) {
            int j = tid + 128 * i;
            int r = j >> 2, c = j & 3;
            cp_async16(Wu + (uint32_t)(r * WROWB + c * 16), src + r * 64 + c * 16);
        }
        CP_COMMIT();
    }

    for (int t = 0; t < 25; t++) {
        if (t < 24) {
            const char* src = (const char*)(g_W2t + (t + 1) * 4096);
            uint32_t wdst = Wu + (uint32_t)(((t + 1) % 3) * WTAP);
#pragma unroll
            for (int i = 0; i < 4; i++) {
                int j = tid + 128 * i;
                int r = j >> 2, c = j & 3;
                cp_async16(wdst + (uint32_t)(r * WROWB + c * 16), src + r * 64 + c * 16);
            }
            CP_COMMIT();
            CP_WAIT1();
        } else {
            CP_WAIT0();
        }
        __syncthreads();

        uint32_t wb = Wu + (uint32_t)((t % 3) * WTAP);
        uint32_t doff = (uint32_t)((t / 5) * 18 + (t % 5)) * ROWB;

#pragma unroll
        for (int kc = 0; kc < 2; kc++) {
            uint32_t ah[4][4];
#pragma unroll
            for (int mi = 0; mi < 4; mi++)
                ldmx4(ah[mi], aBase[mi] + doff + kc * 32);
            uint32_t bh_base = wb + bOff + (uint32_t)(kc * 32);
#pragma unroll
            for (int n = 0; n < 8; n++) {
                uint32_t o = (uint32_t)n * (8 * WROWB);
                uint32_t bh[2], bl[2];
                bh[0] = *(const uint32_t*)(dsm + (bh_base + o - Xu));
                bh[1] = *(const uint32_t*)(dsm + (bh_base + o + 16 - Xu));
                bl[0] = *(const uint32_t*)(dsm + (bh_base + o + 64 * WROWB - Xu));
                bl[1] = *(const uint32_t*)(dsm + (bh_base + o + 64 * WROWB + 16 - Xu));
#pragma unroll
                for (int mi = 0; mi < 4; mi++) {
                    mma16816(acc[mi][n], ah[mi], bh);
                    mma16816(acc[mi][n], ah[mi], bl);
                }
            }
        }
    }
    __syncthreads();

    // epilogue: acc -> prepool P -> pool+bias+relu -> h2 hi/lo
    float* P = (float*)dsm;                  // [64 oc][198]
    int r = l >> 2, c2 = l & 3;
#pragma unroll
    for (int mi = 0; mi < 4; mi++) {
        int s0 = (w * 4 + mi) * 16 + r;
        int s1 = s0 + 8;
#pragma unroll
        for (int n = 0; n < 8; n++) {
            int oc0 = n * 8 + 2 * c2;
            if (s0 < 196) {
                P[oc0 * 198 + s0] = acc[mi][n][0];
                P[(oc0 + 1) * 198 + s0] = acc[mi][n][1];
            }
            if (s1 < 196) {
                P[oc0 * 198 + s1] = acc[mi][n][2];
                P[(oc0 + 1) * 198 + s1] = acc[mi][n][3];
            }
        }
    }
    __syncthreads();
    for (int j = tid; j < 3136; j += 128) {
        int oc = j / 49, q = j % 49;
        int py = q / 7, px = q % 7;
        const float* pp = P + oc * 198 + (2 * py) * 14 + 2 * px;
        float v = fmaxf(fmaxf(pp[0], pp[1]), fmaxf(pp[14], pp[15]));
        v = fmaxf(v + b2[oc], 0.f);
        __half hi = __float2half(v);
        g_h2h[(size_t)b * 3136 + j] = hi;
        g_h2l[(size_t)b * 3136 + j] = __float2half(v - __half2float(hi));
    }
}

// ---------------- FC1 (M=32, N=128 full) + fused FC2 -----------------------
// grid = B/32 CTAs, 256 thr (8 warps: wm 0..1 x wn 0..3), warp tile 16x32.
// K staged 32/iter (98 iters, 3-buffer). Split-fp16 3 products.
// Epilogue: h (32x128) in smem -> fc2 10-way dot -> out.

#define F1ROW  144
#define F1BUF  ((32 + 128) * F1ROW)          // 23040
#define FC1_SMEM (3 * F1BUF)                 // 69120

__global__ __launch_bounds__(256, 2) void fc1_fused(
        const float* __restrict__ bias, const float* __restrict__ W2,
        const float* __restrict__ b2f, float* __restrict__ out) {
    extern __shared__ __align__(16) char fsm[];
    __shared__ float sW2[1280];
    __shared__ float sB2[10];
    __shared__ float sBias[128];
    uint32_t Su = smem_u32(fsm);

    int tid = threadIdx.x;
    int w = tid >> 5, l = tid & 31;
    int wm = w >> 2, wn = w & 3;
    int m0 = blockIdx.x * 32;

    for (int i = tid; i < 1280; i += 256) sW2[i] = W2[i];
    if (tid < 10) sB2[tid] = b2f[tid];
    if (tid < 128) sBias[tid] = bias[tid];

    float acc[4][4];
#pragma unroll
    for (int nt = 0; nt < 4; nt++)
#pragma unroll
        for (int k = 0; k < 4; k++) acc[nt][k] = 0.f;

    // stage k32 chunk kt into buf: 160 rows (32 A + 128 B) x 8 chunks of 16B
    auto stage = [&](int kt, int buf) {
        uint32_t dst0 = Su + (uint32_t)(buf * F1BUF);
        int k0 = kt * 32;
#pragma unroll
        for (int i = 0; i < 5; i++) {
            int j = tid + 256 * i;
            int rrow = j >> 3, c = j & 7;
            const __half* src;
            if (rrow < 32) {
                const __half* base = (c >= 4) ? g_h2l : g_h2h;
                src = base + (size_t)(m0 + rrow) * 3136 + k0 + (c & 3) * 8;
            } else {
                const __half* base = (c >= 4) ? g_F1l : g_F1h;
                src = base + (size_t)(rrow - 32) * 3136 + k0 + (c & 3) * 8;
            }
            uint32_t dst = dst0 + (uint32_t)(rrow * F1ROW + ((c >= 4) ? 64 : 0) + (c & 3) * 16);
            cp_async16(dst, src);
        }
        CP_COMMIT();
    };

    stage(0, 0);

    uint32_t aOff = (uint32_t)((wm * 16 + (l & 15)) * F1ROW + (l >> 4) * 16);
    uint32_t bRow = (uint32_t)(32 + wn * 32 + (l >> 2));
    uint32_t bW0 = (uint32_t)((l & 3) * 4);

    for (int kt = 0; kt < 98; kt++) {
        if (kt < 97) { stage(kt + 1, (kt + 1) % 3); CP_WAIT1(); }
        else CP_WAIT0();
        __syncthreads();
        uint32_t bufo = (uint32_t)((kt % 3) * F1BUF);

#pragma unroll
        for (int kc = 0; kc < 2; kc++) {
            uint32_t ah[4], al[4];
            ldmx4(ah, Su + bufo + aOff + kc * 32);
            ldmx4(al, Su + bufo + aOff + kc * 32 + 64);
#pragma unroll
            for (int nt = 0; nt < 4; nt++) {
                uint32_t rb = bufo + (bRow + nt * 8) * F1ROW + bW0 + kc * 32;
                uint32_t bh[2], bl[2];
                bh[0] = *(const uint32_t*)(fsm + rb);
                bh[1] = *(const uint32_t*)(fsm + rb + 16);
                bl[0] = *(const uint32_t*)(fsm + rb + 64);
                bl[1] = *(const uint32_t*)(fsm + rb + 80);
                mma16816(acc[nt], ah, bh);
                mma16816(acc[nt], ah, bl);
                mma16816(acc[nt], al, bh);
            }
        }
    }

    // epilogue: h rows into smem (reuse buf 0), bias+relu
    float* hP = (float*)fsm;                 // [32][132]
    int r0 = wm * 16 + (l >> 2);
#pragma unroll
    for (int nt = 0; nt < 4; nt++) {
        int col = wn * 32 + nt * 8 + 2 * (l & 3);
        float bs0 = sBias[col], bs1 = sBias[col + 1];
        hP[r0 * 132 + col]       = fmaxf(acc[nt][0] + bs0, 0.f);
        hP[r0 * 132 + col + 1]   = fmaxf(acc[nt][1] + bs1, 0.f);
        hP[(r0 + 8) * 132 + col]     = fmaxf(acc[nt][2] + bs0, 0.f);
        hP[(r0 + 8) * 132 + col + 1] = fmaxf(acc[nt][3] + bs1, 0.f);
    }
    __syncthreads();

    // fc2: 32 rows x 10 outputs
    for (int it = tid; it < 320; it += 256) {
        int r = it / 10, o = it % 10;
        const float* hr = hP + r * 132;
        const float* wr = sW2 + o * 128;
        float s = 0.f;
#pragma unroll
        for (int c = 0; c < 128; c++) s += hr[c] * wr[c];
        out[(size_t)(m0 + r) * 10 + o] = s + sB2[o];
    }
}

// ---------------------------------------------------------------------------

extern "C" void kernel_launch(void* const* d_in, const int* in_sizes, int n_in,
                              void* d_out, int out_size) {
    const float* x    = (const float*)d_in[0];
    const float* w1   = (const float*)d_in[1];
    const float* p1   = (const float*)d_in[2];
    const float* b1   = (const float*)d_in[3];
    const float* w2   = (const float*)d_in[4];
    const float* p2   = (const float*)d_in[5];
    const float* b2   = (const float*)d_in[6];
    const float* fc1w = (const float*)d_in[7];
    const float* fc1b = (const float*)d_in[8];
    const float* fc2w = (const float*)d_in[9];
    const float* fc2b = (const float*)d_in[10];
    float* out = (float*)d_out;

    int B = in_sizes[0] / 784;
    if (B > B_MAX) B = B_MAX;

    zero_k<<<(64 * 32 * 36 + 255) / 256, 256>>>();
    build_k<<<(512 + 65536 + 255) / 256, 256>>>(w1, p1, w2, p2);
    repack_k<<<(102400 + 255) / 256, 256>>>();
    repack_fc1<<<(128 * 3136 + 255) / 256, 256>>>(fc1w);

    conv1_kernel<<<B, 448>>>(x, b1);

    cudaFuncSetAttribute(conv2_mma, cudaFuncAttributeMaxDynamicSharedMemorySize, C2_SMEM);
    conv2_mma<<<B, 128, C2_SMEM>>>(b2);

    cudaFuncSetAttribute(fc1_fused, cudaFuncAttributeMaxDynamicSharedMemorySize, FC1_SMEM);
    fc1_fused<<<B / 32, 256, FC1_SMEM>>>(fc1b, fc2w, fc2b, out);
}

// round 8
// speedup vs baseline: 6.2230x; 1.4109x over previous
#include <cuda_runtime.h>
#include <cuda_fp16.h>
#include <math.h>
#include <stdint.h>

// ---------------------------------------------------------------------------
// SimpleCNN (DCLS) forward, B=4096.
// R7: conv2 1-product (W fp16), fc1 pure-fp16 1-product with k64 staging.
// Precision budget: h1 fp16 (~1e-4) + W2 fp16 (~1e-4) + h2/F1 fp16 (~1.5e-4).
// ---------------------------------------------------------------------------

#define B_MAX 4096

__device__ float g_K1[32 * 36];
__device__ float g_K2[64 * 32 * 36];
__device__ float2 g_W1p[25 * 16];
__device__ __half g_W2t[25 * 64 * 32];           // [tap][oc][ic] fp16
__device__ __half g_h1h[(size_t)B_MAX * 6272];   // conv1 out, fp16
__device__ __half g_h2h[(size_t)B_MAX * 3136];   // conv2 out, fp16
__device__ __half g_F1h[128 * 3136];             // fc1 weights, fp16

__device__ __forceinline__ void fma2(float2& d, const float2& a, const float2& b) {
    asm("fma.rn.f32x2 %0, %1, %2, %0;"
        : "+l"(reinterpret_cast<unsigned long long&>(d))
        : "l"(reinterpret_cast<const unsigned long long&>(a)),
          "l"(reinterpret_cast<const unsigned long long&>(b)));
}

__device__ __forceinline__ uint32_t smem_u32(const void* p) {
    uint32_t a;
    asm("{ .reg .u64 t; cvta.to.shared.u64 t, %1; cvt.u32.u64 %0, t; }" : "=r"(a) : "l"(p));
    return a;
}

__device__ __forceinline__ void ldmx4(uint32_t* r, uint32_t addr) {
    asm volatile("ldmatrix.sync.aligned.m8n8.x4.shared.b16 {%0,%1,%2,%3}, [%4];"
        : "=r"(r[0]), "=r"(r[1]), "=r"(r[2]), "=r"(r[3]) : "r"(addr));
}

__device__ __forceinline__ void mma16816(float* c, const uint32_t* a, const uint32_t* b) {
    asm volatile(
        "mma.sync.aligned.m16n8k16.row.col.f32.f16.f16.f32 "
        "{%0,%1,%2,%3}, {%4,%5,%6,%7}, {%8,%9}, {%0,%1,%2,%3};"
        : "+f"(c[0]), "+f"(c[1]), "+f"(c[2]), "+f"(c[3])
        : "r"(a[0]), "r"(a[1]), "r"(a[2]), "r"(a[3]), "r"(b[0]), "r"(b[1]));
}

__device__ __forceinline__ void cp_async16(uint32_t dst, const void* src) {
    asm volatile("cp.async.ca.shared.global [%0], [%1], 16;" :: "r"(dst), "l"(src));
}
#define CP_COMMIT() asm volatile("cp.async.commit_group;" ::: "memory")
#define CP_WAIT1()  asm volatile("cp.async.wait_group 1;" ::: "memory")
#define CP_WAIT0()  asm volatile("cp.async.wait_group 0;" ::: "memory")

// ---------------- DCLS kernel construction ---------------------------------

__global__ void zero_k() {
    int i = blockIdx.x * blockDim.x + threadIdx.x;
    if (i < 32 * 36) g_K1[i] = 0.f;
    if (i < 64 * 32 * 36) g_K2[i] = 0.f;
}

__device__ __forceinline__ void dcls_scatter(float* grid, float w, float pa, float pb) {
    float p1c = fminf(fmaxf(pa, -2.f), 2.f) + 2.f;
    float p2c = fminf(fmaxf(pb, -2.f), 2.f) + 2.f;
    int i1 = (int)floorf(p1c);
    int i2 = (int)floorf(p2c);
    float r1 = p1c - (float)i1;
    float r2 = p2c - (float)i2;
    atomicAdd(&grid[i1 * 6 + i2],           w * (1.f - r1) * (1.f - r2));
    atomicAdd(&grid[(i1 + 1) * 6 + i2],     w * r1 * (1.f - r2));
    atomicAdd(&grid[i1 * 6 + i2 + 1],       w * (1.f - r1) * r2);
    atomicAdd(&grid[(i1 + 1) * 6 + i2 + 1], w * r1 * r2);
}

__global__ void build_k(const float* __restrict__ w1, const float* __restrict__ p1,
                        const float* __restrict__ w2, const float* __restrict__ p2) {
    int idx = blockIdx.x * blockDim.x + threadIdx.x;
    if (idx < 512) {
        float w = w1[idx];
        int f = idx / 16;
        dcls_scatter(g_K1 + f * 36, w, p1[idx], p1[512 + idx]);
    } else if (idx < 512 + 65536) {
        int e = idx - 512;
        float w = w2[e];
        int f = e / 32;
        dcls_scatter(g_K2 + f * 36, w, p2[e], p2[65536 + e]);
    }
}

__global__ void repack_k() {
    int i = blockIdx.x * blockDim.x + threadIdx.x;
    if (i < 400) {
        int t = i / 16, p = i % 16;
        int tap = (t / 5) * 6 + (t % 5);
        g_W1p[i] = make_float2(g_K1[(2 * p) * 36 + tap], g_K1[(2 * p + 1) * 36 + tap]);
    }
    if (i < 51200) {                         // [tap][oc][ic] fp16
        int t = i / 2048, r = i % 2048;
        int oc = r >> 5, ic = r & 31;
        float w = g_K2[(oc * 32 + ic) * 36 + (t / 5) * 6 + (t % 5)];
        g_W2t[i] = __float2half(w);
    }
}

__global__ void repack_fc1(const float* __restrict__ W) {
    int i = blockIdx.x * blockDim.x + threadIdx.x;
    if (i < 128 * 3136) g_F1h[i] = __float2half(W[i]);
}

// ---------------- conv1 (FFMA2, epilogue -> fp16) --------------------------

__global__ __launch_bounds__(448, 1) void conv1_kernel(const float* __restrict__ x,
                                                       const float* __restrict__ b1) {
    __shared__ float sIn[32 * 32];
    __shared__ float2 sW[25 * 16];
    int tid = threadIdx.x;
    int b = blockIdx.x;

    for (int i = tid; i < 1024; i += 448) sIn[i] = 0.f;
    if (tid < 400) sW[tid] = g_W1p[tid];
    __syncthreads();
    const float* xi = x + b * 784;
    for (int i = tid; i < 784; i += 448) {
        int y = i / 28, c = i % 28;
        sIn[(y + 2) * 32 + c + 2] = xi[i];
    }
    __syncthreads();

    int pair = tid & 15;
    int py = (tid >> 4) % 14;
    int xh = tid / 224;
    int Y = 2 * py, X0 = xh * 14;

    float2 acc[2][14];
#pragma unroll
    for (int r = 0; r < 2; r++)
#pragma unroll
        for (int c = 0; c < 14; c++) acc[r][c] = make_float2(0.f, 0.f);

#pragma unroll
    for (int dyy = 0; dyy < 6; dyy++) {
        const float* rp = sIn + (Y + dyy) * 32 + X0;
        float2 vp[18];
#pragma unroll
        for (int i = 0; i < 18; i++) { float v = rp[i]; vp[i] = make_float2(v, v); }
        if (dyy < 5) {
#pragma unroll
            for (int dx = 0; dx < 5; dx++) {
                float2 w = sW[(dyy * 5 + dx) * 16 + pair];
#pragma unroll
                for (int c = 0; c < 14; c++) fma2(acc[0][c], vp[c + dx], w);
            }
        }
        if (dyy >= 1) {
#pragma unroll
            for (int dx = 0; dx < 5; dx++) {
                float2 w = sW[((dyy - 1) * 5 + dx) * 16 + pair];
#pragma unroll
                for (int c = 0; c < 14; c++) fma2(acc[1][c], vp[c + dx], w);
            }
        }
    }

    int oc0 = 2 * pair;
    float blo = b1[oc0], bhi = b1[oc0 + 1];
    __half* o0 = g_h1h + (size_t)b * 6272 + oc0 * 196 + py * 14 + xh * 7;
    __half* o1 = o0 + 196;
#pragma unroll
    for (int px = 0; px < 7; px++) {
        float2 q0 = acc[0][2 * px], q1 = acc[0][2 * px + 1];
        float2 q2 = acc[1][2 * px], q3 = acc[1][2 * px + 1];
        float mlo = fmaxf(fmaxf(q0.x, q1.x), fmaxf(q2.x, q3.x)) + blo;
        float mhi = fmaxf(fmaxf(q0.y, q1.y), fmaxf(q2.y, q3.y)) + bhi;
        o0[px] = __float2half(fmaxf(mlo, 0.f));
        o1[px] = __float2half(fmaxf(mhi, 0.f));
    }
}

// ---------------- conv2 via mma.sync, 1-product ----------------------------
// CTA = 1 image, 128 thr (4 warps x 4 m16 tiles). X: 324 rows x 80B.
// W fp16: 64 rows x 80B per tap, 3-buffer cp.async.

#define ROWB    80
#define XBYTES  (324 * ROWB)                 // 25920
#define WROWB   80
#define WTAP    (64 * WROWB)                 // 5120
#define C2_SMEM 50688                        // >= epilogue 64*198*4

__global__ __launch_bounds__(128, 2) void conv2_mma(const float* __restrict__ b2) {
    extern __shared__ __align__(16) char dsm[];
    uint32_t Xu = smem_u32(dsm);
    uint32_t Wu = Xu + XBYTES;

    int tid = threadIdx.x;
    int w = tid >> 5, l = tid & 31;
    int b = blockIdx.x;

    for (int i = tid; i < XBYTES / 16; i += 128)
        ((uint4*)dsm)[i] = make_uint4(0u, 0u, 0u, 0u);
    __syncthreads();
    const uint32_t* h1b = (const uint32_t*)(g_h1h + (size_t)b * 6272);
    for (int i = tid; i < 3136; i += 128) {
        uint32_t v = h1b[i];
        int ic = i / 98, p = i % 98;
        int s = 2 * p;
        int y = s / 14, x = s % 14;
        int g = (y + 2) * 18 + (x + 2);
        *(uint16_t*)(dsm + g * ROWB + 2 * ic) = (uint16_t)(v & 0xFFFF);
        *(uint16_t*)(dsm + (g + 1) * ROWB + 2 * ic) = (uint16_t)(v >> 16);
    }

    int row = l & 15, kh = l >> 4;
    uint32_t aBase[4];
#pragma unroll
    for (int mi = 0; mi < 4; mi++) {
        int s = (w * 4 + mi) * 16 + row;
        if (s > 195) s = 0;
        int g0 = (s / 14) * 18 + (s % 14);
        aBase[mi] = Xu + (uint32_t)g0 * ROWB + (uint32_t)kh * 16;
    }
    uint32_t bOff = (uint32_t)((l >> 2) * WROWB + (l & 3) * 4);

    float acc[4][8][4];
#pragma unroll
    for (int mi = 0; mi < 4; mi++)
#pragma unroll
        for (int n = 0; n < 8; n++)
#pragma unroll
            for (int k = 0; k < 4; k++) acc[mi][n][k] = 0.f;

    // stage tap 0 into buf 0: 64 rows x 4 x 16B = 256 chunks, 2/thread
    {
        const char* src = (const char*)g_W2t;
#pragma unroll
        for (int i = 0; i < 2; i++) {
            int j = tid + 128 * i;
            int r = j >> 2, c = j & 3;
            cp_async16(Wu + (uint32_t)(r * WROWB + c * 16), src + r * 64 + c * 16);
        }
        CP_COMMIT();
    }

    for (int t = 0; t < 25; t++) {
        if (t < 24) {
            const char* src = (const char*)(g_W2t + (t + 1) * 2048);
            uint32_t wdst = Wu + (uint32_t)(((t + 1) % 3) * WTAP);
#pragma unroll
            for (int i = 0; i < 2; i++) {
                int j = tid + 128 * i;
                int r = j >> 2, c = j & 3;
                cp_async16(wdst + (uint32_t)(r * WROWB + c * 16), src + r * 64 + c * 16);
            }
            CP_COMMIT();
            CP_WAIT1();
        } else {
            CP_WAIT0();
        }
        __syncthreads();

        uint32_t wb = Wu + (uint32_t)((t % 3) * WTAP);
        uint32_t doff = (uint32_t)((t / 5) * 18 + (t % 5)) * ROWB;

#pragma unroll
        for (int kc = 0; kc < 2; kc++) {
            uint32_t ah[4][4];
#pragma unroll
            for (int mi = 0; mi < 4; mi++)
                ldmx4(ah[mi], aBase[mi] + doff + kc * 32);
            uint32_t bh_base = wb + bOff + (uint32_t)(kc * 32);
#pragma unroll
            for (int n = 0; n < 8; n++) {
                uint32_t o = (uint32_t)n * (8 * WROWB);
                uint32_t bh[2];
                bh[0] = *(const uint32_t*)(dsm + (bh_base + o - Xu));
                bh[1] = *(const uint32_t*)(dsm + (bh_base + o + 16 - Xu));
#pragma unroll
                for (int mi = 0; mi < 4; mi++)
                    mma16816(acc[mi][n], ah[mi], bh);
            }
        }
    }
    __syncthreads();

    // epilogue: acc -> prepool P -> pool+bias+relu -> h2 fp16
    float* P = (float*)dsm;                  // [64 oc][198]
    int r = l >> 2, c2 = l & 3;
#pragma unroll
    for (int mi = 0; mi < 4; mi++) {
        int s0 = (w * 4 + mi) * 16 + r;
        int s1 = s0 + 8;
#pragma unroll
        for (int n = 0; n < 8; n++) {
            int oc0 = n * 8 + 2 * c2;
            if (s0 < 196) {
                P[oc0 * 198 + s0] = acc[mi][n][0];
                P[(oc0 + 1) * 198 + s0] = acc[mi][n][1];
            }
            if (s1 < 196) {
                P[oc0 * 198 + s1] = acc[mi][n][2];
                P[(oc0 + 1) * 198 + s1] = acc[mi][n][3];
            }
        }
    }
    __syncthreads();
    for (int j = tid; j < 3136; j += 128) {
        int oc = j / 49, q = j % 49;
        int py = q / 7, px = q % 7;
        const float* pp = P + oc * 198 + (2 * py) * 14 + 2 * px;
        float v = fmaxf(fmaxf(pp[0], pp[1]), fmaxf(pp[14], pp[15]));
        g_h2h[(size_t)b * 3136 + j] = __float2half(fmaxf(v + b2[oc], 0.f));
    }
}

// ---------------- FC1 (M=32, N=128, pure fp16) + fused FC2 -----------------
// grid = B/32, 256 thr (8 warps: 2m x 4n), warp tile 16x32. k64/iter, 49 iters.

#define F1ROW  144
#define F1BUF  ((32 + 128) * F1ROW)          // 23040
#define FC1_SMEM (3 * F1BUF)                 // 69120

__global__ __launch_bounds__(256, 2) void fc1_fused(
        const float* __restrict__ bias, const float* __restrict__ W2,
        const float* __restrict__ b2f, float* __restrict__ out) {
    extern __shared__ __align__(16) char fsm[];
    __shared__ float sW2[1280];
    __shared__ float sB2[10];
    __shared__ float sBias[128];
    uint32_t Su = smem_u32(fsm);

    int tid = threadIdx.x;
    int w = tid >> 5, l = tid & 31;
    int wm = w >> 2, wn = w & 3;
    int m0 = blockIdx.x * 32;

    for (int i = tid; i < 1280; i += 256) sW2[i] = W2[i];
    if (tid < 10) sB2[tid] = b2f[tid];
    if (tid < 128) sBias[tid] = bias[tid];

    float acc[4][4];
#pragma unroll
    for (int nt = 0; nt < 4; nt++)
#pragma unroll
        for (int k = 0; k < 4; k++) acc[nt][k] = 0.f;

    // stage k64 chunk: 160 rows x 8 x 16B = 1280 chunks, 5/thread
    auto stage = [&](int kt, int buf) {
        uint32_t dst0 = Su + (uint32_t)(buf * F1BUF);
        int k0 = kt * 64;
#pragma unroll
        for (int i = 0; i < 5; i++) {
            int j = tid + 256 * i;
            int rrow = j >> 3, c = j & 7;
            const __half* src = (rrow < 32)
                ? g_h2h + (size_t)(m0 + rrow) * 3136 + k0 + c * 8
                : g_F1h + (size_t)(rrow - 32) * 3136 + k0 + c * 8;
            cp_async16(dst0 + (uint32_t)(rrow * F1ROW + c * 16), src);
        }
        CP_COMMIT();
    };

    stage(0, 0);

    uint32_t aOff = (uint32_t)((wm * 16 + (l & 15)) * F1ROW + (l >> 4) * 16);
    uint32_t bRow = (uint32_t)(32 + wn * 32 + (l >> 2));
    uint32_t bW0 = (uint32_t)((l & 3) * 4);

    for (int kt = 0; kt < 49; kt++) {
        if (kt < 48) { stage(kt + 1, (kt + 1) % 3); CP_WAIT1(); }
        else CP_WAIT0();
        __syncthreads();
        uint32_t bufo = (uint32_t)((kt % 3) * F1BUF);

#pragma unroll
        for (int kc = 0; kc < 4; kc++) {
            uint32_t ah[4];
            ldmx4(ah, Su + bufo + aOff + kc * 32);
#pragma unroll
            for (int nt = 0; nt < 4; nt++) {
                uint32_t rb = bufo + (bRow + nt * 8) * F1ROW + bW0 + kc * 32;
                uint32_t bh[2];
                bh[0] = *(const uint32_t*)(fsm + rb);
                bh[1] = *(const uint32_t*)(fsm + rb + 16);
                mma16816(acc[nt], ah, bh);
            }
        }
        __syncthreads();
    }

    // epilogue: h rows -> smem, bias+relu, then fc2 dot
    float* hP = (float*)fsm;                 // [32][132]
    int r0 = wm * 16 + (l >> 2);
#pragma unroll
    for (int nt = 0; nt < 4; nt++) {
        int col = wn * 32 + nt * 8 + 2 * (l & 3);
        float bs0 = sBias[col], bs1 = sBias[col + 1];
        hP[r0 * 132 + col]       = fmaxf(acc[nt][0] + bs0, 0.f);
        hP[r0 * 132 + col + 1]   = fmaxf(acc[nt][1] + bs1, 0.f);
        hP[(r0 + 8) * 132 + col]     = fmaxf(acc[nt][2] + bs0, 0.f);
        hP[(r0 + 8) * 132 + col + 1] = fmaxf(acc[nt][3] + bs1, 0.f);
    }
    __syncthreads();

    for (int it = tid; it < 320; it += 256) {
        int r = it / 10, o = it % 10;
        const float* hr = hP + r * 132;
        const float* wr = sW2 + o * 128;
        float s = 0.f;
#pragma unroll
        for (int c = 0; c < 128; c++) s += hr[c] * wr[c];
        out[(size_t)(m0 + r) * 10 + o] = s + sB2[o];
    }
}

// ---------------------------------------------------------------------------

extern "C" void kernel_launch(void* const* d_in, const int* in_sizes, int n_in,
                              void* d_out, int out_size) {
    const float* x    = (const float*)d_in[0];
    const float* w1   = (const float*)d_in[1];
    const float* p1   = (const float*)d_in[2];
    const float* b1   = (const float*)d_in[3];
    const float* w2   = (const float*)d_in[4];
    const float* p2   = (const float*)d_in[5];
    const float* b2   = (const float*)d_in[6];
    const float* fc1w = (const float*)d_in[7];
    const float* fc1b = (const float*)d_in[8];
    const float* fc2w = (const float*)d_in[9];
    const float* fc2b = (const float*)d_in[10];
    float* out = (float*)d_out;

    int B = in_sizes[0] / 784;
    if (B > B_MAX) B = B_MAX;

    zero_k<<<(64 * 32 * 36 + 255) / 256, 256>>>();
    build_k<<<(512 + 65536 + 255) / 256, 256>>>(w1, p1, w2, p2);
    repack_k<<<(51200 + 255) / 256, 256>>>();
    repack_fc1<<<(128 * 3136 + 255) / 256, 256>>>(fc1w);

    conv1_kernel<<<B, 448>>>(x, b1);

    cudaFuncSetAttribute(conv2_mma, cudaFuncAttributeMaxDynamicSharedMemorySize, C2_SMEM);
    conv2_mma<<<B, 128, C2_SMEM>>>(b2);

    cudaFuncSetAttribute(fc1_fused, cudaFuncAttributeMaxDynamicSharedMemorySize, FC1_SMEM);
    fc1_fused<<<B / 32, 256, FC1_SMEM>>>(fc1b, fc2w, fc2b, out);
}

// round 10
// speedup vs baseline: 7.2291x; 1.1617x over previous
#include <cuda_runtime.h>
#include <cuda_fp16.h>
#include <math.h>
#include <stdint.h>

// ---------------------------------------------------------------------------
// SimpleCNN (DCLS) forward, B=4096.
// R9: conv1+conv2 fused, one CTA per image. conv1 = mma.sync over taps (K=32)
// with quad-ordered M so maxpool is a register shuffle; pooled output written
// directly into conv2's SMEM X layout (h1 never touches HBM).
// ---------------------------------------------------------------------------

#define B_MAX 4096

__device__ float g_K1[32 * 36];
__device__ float g_K2[64 * 32 * 36];
__device__ __half g_W1t[32 * 32];                // [oc][tap(25,pad32)] fp16
__device__ __half g_W2t[25 * 64 * 32];           // [tap][oc][ic] fp16
__device__ __half g_h2h[(size_t)B_MAX * 3136];   // conv2 out, fp16
__device__ __half g_F1h[128 * 3136];             // fc1 weights, fp16

__device__ __forceinline__ uint32_t smem_u32(const void* p) {
    uint32_t a;
    asm("{ .reg .u64 t; cvta.to.shared.u64 t, %1; cvt.u32.u64 %0, t; }" : "=r"(a) : "l"(p));
    return a;
}

__device__ __forceinline__ void ldmx4(uint32_t* r, uint32_t addr) {
    asm volatile("ldmatrix.sync.aligned.m8n8.x4.shared.b16 {%0,%1,%2,%3}, [%4];"
        : "=r"(r[0]), "=r"(r[1]), "=r"(r[2]), "=r"(r[3]) : "r"(addr));
}

__device__ __forceinline__ void mma16816(float* c, const uint32_t* a, const uint32_t* b) {
    asm volatile(
        "mma.sync.aligned.m16n8k16.row.col.f32.f16.f16.f32 "
        "{%0,%1,%2,%3}, {%4,%5,%6,%7}, {%8,%9}, {%0,%1,%2,%3};"
        : "+f"(c[0]), "+f"(c[1]), "+f"(c[2]), "+f"(c[3])
        : "r"(a[0]), "r"(a[1]), "r"(a[2]), "r"(a[3]), "r"(b[0]), "r"(b[1]));
}

__device__ __forceinline__ void cp_async16(uint32_t dst, const void* src) {
    asm volatile("cp.async.ca.shared.global [%0], [%1], 16;" :: "r"(dst), "l"(src));
}
#define CP_COMMIT() asm volatile("cp.async.commit_group;" ::: "memory")
#define CP_WAIT1()  asm volatile("cp.async.wait_group 1;" ::: "memory")
#define CP_WAIT0()  asm volatile("cp.async.wait_group 0;" ::: "memory")

__device__ __forceinline__ float rmax4(float v) {
    v = fmaxf(v, __shfl_xor_sync(0xFFFFFFFFu, v, 4));
    v = fmaxf(v, __shfl_xor_sync(0xFFFFFFFFu, v, 8));
    return v;
}

// ---------------- DCLS kernel construction ---------------------------------

__global__ void zero_k() {
    int i = blockIdx.x * blockDim.x + threadIdx.x;
    if (i < 32 * 36) g_K1[i] = 0.f;
    if (i < 64 * 32 * 36) g_K2[i] = 0.f;
}

__device__ __forceinline__ void dcls_scatter(float* grid, float w, float pa, float pb) {
    float p1c = fminf(fmaxf(pa, -2.f), 2.f) + 2.f;
    float p2c = fminf(fmaxf(pb, -2.f), 2.f) + 2.f;
    int i1 = (int)floorf(p1c);
    int i2 = (int)floorf(p2c);
    float r1 = p1c - (float)i1;
    float r2 = p2c - (float)i2;
    atomicAdd(&grid[i1 * 6 + i2],           w * (1.f - r1) * (1.f - r2));
    atomicAdd(&grid[(i1 + 1) * 6 + i2],     w * r1 * (1.f - r2));
    atomicAdd(&grid[i1 * 6 + i2 + 1],       w * (1.f - r1) * r2);
    atomicAdd(&grid[(i1 + 1) * 6 + i2 + 1], w * r1 * r2);
}

__global__ void build_k(const float* __restrict__ w1, const float* __restrict__ p1,
                        const float* __restrict__ w2, const float* __restrict__ p2) {
    int idx = blockIdx.x * blockDim.x + threadIdx.x;
    if (idx < 512) {
        float w = w1[idx];
        int f = idx / 16;
        dcls_scatter(g_K1 + f * 36, w, p1[idx], p1[512 + idx]);
    } else if (idx < 512 + 65536) {
        int e = idx - 512;
        float w = w2[e];
        int f = e / 32;
        dcls_scatter(g_K2 + f * 36, w, p2[e], p2[65536 + e]);
    }
}

__global__ void repack_all(const float* __restrict__ W) {
    int i = blockIdx.x * blockDim.x + threadIdx.x;
    if (i < 1024) {                          // W1t [oc][tap 25 pad 32]
        int oc = i >> 5, t = i & 31;
        float w = (t < 25) ? g_K1[oc * 36 + (t / 5) * 6 + (t % 5)] : 0.f;
        g_W1t[i] = __float2half(w);
    }
    if (i < 51200) {                         // W2t [tap][oc][ic]
        int t = i / 2048, r = i % 2048;
        int oc = r >> 5, ic = r & 31;
        float w = g_K2[(oc * 32 + ic) * 36 + (t / 5) * 6 + (t % 5)];
        g_W2t[i] = __float2half(w);
    }
    if (i < 128 * 3136) g_F1h[i] = __float2half(W[i]);
}

// ---------------- fused conv1 + pool + conv2 + pool ------------------------
// CTA = 1 image, 128 thr (4 warps).
// SMEM map (bytes): Xpad [32x32 half] @0..2048 | W1 [32x80] @2048..4608 |
//   A scratch 4x[16x80] @4608..9728 | X2 [324x80] @9728..35648 |
//   W2 3-buf @35648..51008.  Epilogue P [64x198 f32] reuses @0 (50688 B).

#define XP_OFF   0
#define W1_OFF   2048
#define A_OFF    4608
#define X2_OFF   9728
#define W2_OFF   35648
#define WROWB    80
#define WTAP     (64 * WROWB)                // 5120
#define C2_SMEM  51008

__global__ __launch_bounds__(128, 2) void fused_conv(const float* __restrict__ x,
                                                     const float* __restrict__ b1,
                                                     const float* __restrict__ b2) {
    extern __shared__ __align__(16) char dsm[];
    __shared__ float sB1[32];
    uint32_t Su = smem_u32(dsm);

    int tid = threadIdx.x;
    int w = tid >> 5, l = tid & 31;
    int b = blockIdx.x;

    // zero Xpad..X2 regions (covers padding borders)
    for (int i = tid; i < W2_OFF / 16; i += 128)
        ((uint4*)dsm)[i] = make_uint4(0u, 0u, 0u, 0u);
    // stage conv2 tap-0 weights (independent of zeroing: W2 region untouched)
    {
        const char* src = (const char*)g_W2t;
#pragma unroll
        for (int i = 0; i < 2; i++) {
            int j = tid + 128 * i;
            int r = j >> 2, c = j & 3;
            cp_async16(Su + W2_OFF + (uint32_t)(r * WROWB + c * 16), src + r * 64 + c * 16);
        }
        CP_COMMIT();
    }
    if (tid < 32) sB1[tid] = b1[tid];
    __syncthreads();

    // fill Xpad fp16 and W1
    const float* xi = x + (size_t)b * 784;
    for (int i = tid; i < 784; i += 128) {
        int y = i / 28, c = i % 28;
        *((__half*)(dsm + XP_OFF) + (y + 2) * 32 + c + 2) = __float2half(xi[i]);
    }
    {
        const uint32_t* w1s = (const uint32_t*)g_W1t;     // 512 u32
        for (int i = tid; i < 512; i += 128) {
            int r = i >> 4, c = i & 15;
            *(uint32_t*)(dsm + W1_OFF + r * 80 + c * 4) = w1s[i];
        }
    }
    __syncthreads();

    // ---- conv1 phase: per-warp m16 tiles over quad-ordered sites ----
    {
        int T0 = (w == 0) ? 0 : (13 + (w - 1) * 12);
        int nT = (w == 0) ? 13 : 12;
        uint32_t AwB = (uint32_t)(A_OFF + w * 1280);
        uint32_t AwU = Su + AwB;
        const __half* XPh = (const __half*)(dsm + XP_OFF);

        for (int Ti = 0; Ti < nT; Ti++) {
            int T = T0 + Ti;
            // fill A[w]: rows=16 sites (quad order), cols=25 taps
            for (int j = l; j < 80; j += 32) {
                int sl = j / 5, dy = j % 5;
                int sp = T * 16 + sl;
                int p = sp >> 2, sub = sp & 3;
                int y = 2 * (p / 14) + (sub >> 1);
                int xx = 2 * (p % 14) + (sub & 1);
                const __half* sr = XPh + (y + dy) * 32 + xx;
                __half* dr = (__half*)(dsm + AwB + sl * 80) + dy * 5;
                dr[0] = sr[0]; dr[1] = sr[1]; dr[2] = sr[2]; dr[3] = sr[3]; dr[4] = sr[4];
            }
            __syncwarp();
            uint32_t a0[4], a1[4];
            ldmx4(a0, AwU + (uint32_t)((l & 15) * 80 + (l >> 4) * 16));
            ldmx4(a1, AwU + (uint32_t)((l & 15) * 80 + 32 + (l >> 4) * 16));
            __syncwarp();

#pragma unroll
            for (int n = 0; n < 4; n++) {
                const char* wr = dsm + W1_OFF + (n * 8 + (l >> 2)) * 80 + (l & 3) * 4;
                uint32_t b0[2] = { *(const uint32_t*)wr, *(const uint32_t*)(wr + 16) };
                uint32_t b1f[2] = { *(const uint32_t*)(wr + 32), *(const uint32_t*)(wr + 48) };
                float acc[4] = {0.f, 0.f, 0.f, 0.f};
                mma16816(acc, a0, b0);
                mma16816(acc, a1, b1f);
                // pool via shuffles: rows 4q..4q+3 -> quad q
                float c0 = rmax4(acc[0]), c1 = rmax4(acc[1]);
                float c2 = rmax4(acc[2]), c3 = rmax4(acc[3]);
                if ((l & 12) == 0) {
                    int oc0 = n * 8 + 2 * (l & 3);
                    float bb0 = sB1[oc0], bb1 = sB1[oc0 + 1];
                    int qa = 4 * T + (l >> 4);
                    int qb = qa + 2;
                    int ga = (qa / 14 + 2) * 18 + (qa % 14) + 2;
                    int gb = (qb / 14 + 2) * 18 + (qb % 14) + 2;
                    __half2 ha = __floats2half2_rn(fmaxf(c0 + bb0, 0.f), fmaxf(c1 + bb1, 0.f));
                    __half2 hb = __floats2half2_rn(fmaxf(c2 + bb0, 0.f), fmaxf(c3 + bb1, 0.f));
                    *(__half2*)(dsm + X2_OFF + ga * 80 + 2 * oc0) = ha;
                    *(__half2*)(dsm + X2_OFF + gb * 80 + 2 * oc0) = hb;
                }
            }
        }
    }
    __syncthreads();

    // ---- conv2 phase (tap-accumulated GEMM, as R7) ----
    uint32_t Xu = Su + X2_OFF;
    uint32_t Wu = Su + W2_OFF;

    int row = l & 15, kh = l >> 4;
    uint32_t aBase[4];
#pragma unroll
    for (int mi = 0; mi < 4; mi++) {
        int s = (w * 4 + mi) * 16 + row;
        if (s > 195) s = 0;
        int g0 = (s / 14) * 18 + (s % 14);
        aBase[mi] = Xu + (uint32_t)g0 * 80 + (uint32_t)kh * 16;
    }
    uint32_t bOff = (uint32_t)((l >> 2) * WROWB + (l & 3) * 4);

    float acc[4][8][4];
#pragma unroll
    for (int mi = 0; mi < 4; mi++)
#pragma unroll
        for (int n = 0; n < 8; n++)
#pragma unroll
            for (int k = 0; k < 4; k++) acc[mi][n][k] = 0.f;

    for (int t = 0; t < 25; t++) {
        if (t < 24) {
            const char* src = (const char*)(g_W2t + (t + 1) * 2048);
            uint32_t wdst = Wu + (uint32_t)(((t + 1) % 3) * WTAP);
#pragma unroll
            for (int i = 0; i < 2; i++) {
                int j = tid + 128 * i;
                int r = j >> 2, c = j & 3;
                cp_async16(wdst + (uint32_t)(r * WROWB + c * 16), src + r * 64 + c * 16);
            }
            CP_COMMIT();
            CP_WAIT1();
        } else {
            CP_WAIT0();
        }
        __syncthreads();

        uint32_t wb = Wu + (uint32_t)((t % 3) * WTAP);
        uint32_t doff = (uint32_t)((t / 5) * 18 + (t % 5)) * 80;

#pragma unroll
        for (int kc = 0; kc < 2; kc++) {
            uint32_t ah[4][4];
#pragma unroll
            for (int mi = 0; mi < 4; mi++)
                ldmx4(ah[mi], aBase[mi] + doff + kc * 32);
            uint32_t bh_base = wb + bOff + (uint32_t)(kc * 32);
#pragma unroll
            for (int n = 0; n < 8; n++) {
                uint32_t o = (uint32_t)n * (8 * WROWB);
                uint32_t bh[2];
                bh[0] = *(const uint32_t*)(dsm + (bh_base + o - Su));
                bh[1] = *(const uint32_t*)(dsm + (bh_base + o + 16 - Su));
#pragma unroll
                for (int mi = 0; mi < 4; mi++)
                    mma16816(acc[mi][n], ah[mi], bh);
            }
        }
    }
    __syncthreads();

    // ---- epilogue: acc -> prepool P -> pool+bias+relu -> h2 fp16 ----
    float* P = (float*)dsm;                  // [64 oc][198]
    int r = l >> 2, c2 = l & 3;
#pragma unroll
    for (int mi = 0; mi < 4; mi++) {
        int s0 = (w * 4 + mi) * 16 + r;
        int s1 = s0 + 8;
#pragma unroll
        for (int n = 0; n < 8; n++) {
            int oc0 = n * 8 + 2 * c2;
            if (s0 < 196) {
                P[oc0 * 198 + s0] = acc[mi][n][0];
                P[(oc0 + 1) * 198 + s0] = acc[mi][n][1];
            }
            if (s1 < 196) {
                P[oc0 * 198 + s1] = acc[mi][n][2];
                P[(oc0 + 1) * 198 + s1] = acc[mi][n][3];
            }
        }
    }
    __syncthreads();
    for (int j = tid; j < 3136; j += 128) {
        int oc = j / 49, q = j % 49;
        int py = q / 7, px = q % 7;
        const float* pp = P + oc * 198 + (2 * py) * 14 + 2 * px;
        float v = fmaxf(fmaxf(pp[0], pp[1]), fmaxf(pp[14], pp[15]));
        g_h2h[(size_t)b * 3136 + j] = __float2half(fmaxf(v + b2[oc], 0.f));
    }
}

// ---------------- FC1 (M=32, N=128, pure fp16) + fused FC2 -----------------

#define F1ROW  144
#define F1BUF  ((32 + 128) * F1ROW)          // 23040
#define FC1_SMEM (3 * F1BUF)                 // 69120

__global__ __launch_bounds__(256, 2) void fc1_fused(
        const float* __restrict__ bias, const float* __restrict__ W2,
        const float* __restrict__ b2f, float* __restrict__ out) {
    extern __shared__ __align__(16) char fsm[];
    __shared__ float sW2[1280];
    __shared__ float sB2[10];
    __shared__ float sBias[128];
    uint32_t Su = smem_u32(fsm);

    int tid = threadIdx.x;
    int w = tid >> 5, l = tid & 31;
    int wm = w >> 2, wn = w & 3;
    int m0 = blockIdx.x * 32;

    for (int i = tid; i < 1280; i += 256) sW2[i] = W2[i];
    if (tid < 10) sB2[tid] = b2f[tid];
    if (tid < 128) sBias[tid] = bias[tid];

    float acc[4][4];
#pragma unroll
    for (int nt = 0; nt < 4; nt++)
#pragma unroll
        for (int k = 0; k < 4; k++) acc[nt][k] = 0.f;

    auto stage = [&](int kt, int buf) {
        uint32_t dst0 = Su + (uint32_t)(buf * F1BUF);
        int k0 = kt * 64;
#pragma unroll
        for (int i = 0; i < 5; i++) {
            int j = tid + 256 * i;
            int rrow = j >> 3, c = j & 7;
            const __half* src = (rrow < 32)
                ? g_h2h + (size_t)(m0 + rrow) * 3136 + k0 + c * 8
                : g_F1h + (size_t)(rrow - 32) * 3136 + k0 + c * 8;
            cp_async16(dst0 + (uint32_t)(rrow * F1ROW + c * 16), src);
        }
        CP_COMMIT();
    };

    stage(0, 0);

    uint32_t aOff = (uint32_t)((wm * 16 + (l & 15)) * F1ROW + (l >> 4) * 16);
    uint32_t bRow = (uint32_t)(32 + wn * 32 + (l >> 2));
    uint32_t bW0 = (uint32_t)((l & 3) * 4);

    for (int kt = 0; kt < 49; kt++) {
        if (kt < 48) { stage(kt + 1, (kt + 1) % 3); CP_WAIT1(); }
        else CP_WAIT0();
        __syncthreads();
        uint32_t bufo = (uint32_t)((kt % 3) * F1BUF);

#pragma unroll
        for (int kc = 0; kc < 4; kc++) {
            uint32_t ah[4];
            ldmx4(ah, Su + bufo + aOff + kc * 32);
#pragma unroll
            for (int nt = 0; nt < 4; nt++) {
                uint32_t rb = bufo + (bRow + nt * 8) * F1ROW + bW0 + kc * 32;
                uint32_t bh[2];
                bh[0] = *(const uint32_t*)(fsm + rb);
                bh[1] = *(const uint32_t*)(fsm + rb + 16);
                mma16816(acc[nt], ah, bh);
            }
        }
        __syncthreads();
    }

    float* hP = (float*)fsm;                 // [32][132]
    int r0 = wm * 16 + (l >> 2);
#pragma unroll
    for (int nt = 0; nt < 4; nt++) {
        int col = wn * 32 + nt * 8 + 2 * (l & 3);
        float bs0 = sBias[col], bs1 = sBias[col + 1];
        hP[r0 * 132 + col]       = fmaxf(acc[nt][0] + bs0, 0.f);
        hP[r0 * 132 + col + 1]   = fmaxf(acc[nt][1] + bs1, 0.f);
        hP[(r0 + 8) * 132 + col]     = fmaxf(acc[nt][2] + bs0, 0.f);
        hP[(r0 + 8) * 132 + col + 1] = fmaxf(acc[nt][3] + bs1, 0.f);
    }
    __syncthreads();

    for (int it = tid; it < 320; it += 256) {
        int r = it / 10, o = it % 10;
        const float* hr = hP + r * 132;
        const float* wr = sW2 + o * 128;
        float s = 0.f;
#pragma unroll
        for (int c = 0; c < 128; c++) s += hr[c] * wr[c];
        out[(size_t)(m0 + r) * 10 + o] = s + sB2[o];
    }
}

// ---------------------------------------------------------------------------

extern "C" void kernel_launch(void* const* d_in, const int* in_sizes, int n_in,
                              void* d_out, int out_size) {
    const float* x    = (const float*)d_in[0];
    const float* w1   = (const float*)d_in[1];
    const float* p1   = (const float*)d_in[2];
    const float* b1   = (const float*)d_in[3];
    const float* w2   = (const float*)d_in[4];
    const float* p2   = (const float*)d_in[5];
    const float* b2   = (const float*)d_in[6];
    const float* fc1w = (const float*)d_in[7];
    const float* fc1b = (const float*)d_in[8];
    const float* fc2w = (const float*)d_in[9];
    const float* fc2b = (const float*)d_in[10];
    float* out = (float*)d_out;

    int B = in_sizes[0] / 784;
    if (B > B_MAX) B = B_MAX;

    zero_k<<<(64 * 32 * 36 + 255) / 256, 256>>>();
    build_k<<<(512 + 65536 + 255) / 256, 256>>>(w1, p1, w2, p2);
    repack_all<<<(128 * 3136 + 255) / 256, 256>>>(fc1w);

    cudaFuncSetAttribute(fused_conv, cudaFuncAttributeMaxDynamicSharedMemorySize, C2_SMEM);
    fused_conv<<<B, 128, C2_SMEM>>>(x, b1, b2);

    cudaFuncSetAttribute(fc1_fused, cudaFuncAttributeMaxDynamicSharedMemorySize, FC1_SMEM);
    fc1_fused<<<B / 32, 256, FC1_SMEM>>>(fc1b, fc2w, fc2b, out);
}

// round 12
// speedup vs baseline: 7.5965x; 1.0508x over previous
#include <cuda_runtime.h>
#include <cuda_fp16.h>
#include <math.h>
#include <stdint.h>

// ---------------------------------------------------------------------------
// SimpleCNN (DCLS) forward, B=4096.
// R12: R11 retile (8 warps = 4m x 2n, 64 acc regs, occ 25%) with the conv1
// tile-loop bound fixed: T < 49 (49 m16-tiles cover all 784 conv1 sites).
// ---------------------------------------------------------------------------

#define B_MAX 4096

__device__ float g_K1[32 * 36];
__device__ float g_K2[64 * 32 * 36];
__device__ __half g_W1t[32 * 32];                // [oc][tap(25,pad32)] fp16
__device__ __half g_W2t[25 * 64 * 32];           // [tap][oc][ic] fp16
__device__ __half g_h2h[(size_t)B_MAX * 3136];   // conv2 out, fp16
__device__ __half g_F1h[128 * 3136];             // fc1 weights, fp16

__device__ __forceinline__ uint32_t smem_u32(const void* p) {
    uint32_t a;
    asm("{ .reg .u64 t; cvta.to.shared.u64 t, %1; cvt.u32.u64 %0, t; }" : "=r"(a) : "l"(p));
    return a;
}

__device__ __forceinline__ void ldmx4(uint32_t* r, uint32_t addr) {
    asm volatile("ldmatrix.sync.aligned.m8n8.x4.shared.b16 {%0,%1,%2,%3}, [%4];"
        : "=r"(r[0]), "=r"(r[1]), "=r"(r[2]), "=r"(r[3]) : "r"(addr));
}

__device__ __forceinline__ void mma16816(float* c, const uint32_t* a, const uint32_t* b) {
    asm volatile(
        "mma.sync.aligned.m16n8k16.row.col.f32.f16.f16.f32 "
        "{%0,%1,%2,%3}, {%4,%5,%6,%7}, {%8,%9}, {%0,%1,%2,%3};"
        : "+f"(c[0]), "+f"(c[1]), "+f"(c[2]), "+f"(c[3])
        : "r"(a[0]), "r"(a[1]), "r"(a[2]), "r"(a[3]), "r"(b[0]), "r"(b[1]));
}

__device__ __forceinline__ void cp_async16(uint32_t dst, const void* src) {
    asm volatile("cp.async.ca.shared.global [%0], [%1], 16;" :: "r"(dst), "l"(src));
}
#define CP_COMMIT() asm volatile("cp.async.commit_group;" ::: "memory")
#define CP_WAIT1()  asm volatile("cp.async.wait_group 1;" ::: "memory")
#define CP_WAIT0()  asm volatile("cp.async.wait_group 0;" ::: "memory")

__device__ __forceinline__ float rmax4(float v) {
    v = fmaxf(v, __shfl_xor_sync(0xFFFFFFFFu, v, 4));
    v = fmaxf(v, __shfl_xor_sync(0xFFFFFFFFu, v, 8));
    return v;
}

// ---------------- DCLS kernel construction ---------------------------------

__global__ void zero_k() {
    int i = blockIdx.x * blockDim.x + threadIdx.x;
    if (i < 32 * 36) g_K1[i] = 0.f;
    if (i < 64 * 32 * 36) g_K2[i] = 0.f;
}

__device__ __forceinline__ void dcls_scatter(float* grid, float w, float pa, float pb) {
    float p1c = fminf(fmaxf(pa, -2.f), 2.f) + 2.f;
    float p2c = fminf(fmaxf(pb, -2.f), 2.f) + 2.f;
    int i1 = (int)floorf(p1c);
    int i2 = (int)floorf(p2c);
    float r1 = p1c - (float)i1;
    float r2 = p2c - (float)i2;
    atomicAdd(&grid[i1 * 6 + i2],           w * (1.f - r1) * (1.f - r2));
    atomicAdd(&grid[(i1 + 1) * 6 + i2],     w * r1 * (1.f - r2));
    atomicAdd(&grid[i1 * 6 + i2 + 1],       w * (1.f - r1) * r2);
    atomicAdd(&grid[(i1 + 1) * 6 + i2 + 1], w * r1 * r2);
}

__global__ void build_k(const float* __restrict__ w1, const float* __restrict__ p1,
                        const float* __restrict__ w2, const float* __restrict__ p2) {
    int idx = blockIdx.x * blockDim.x + threadIdx.x;
    if (idx < 512) {
        float w = w1[idx];
        int f = idx / 16;
        dcls_scatter(g_K1 + f * 36, w, p1[idx], p1[512 + idx]);
    } else if (idx < 512 + 65536) {
        int e = idx - 512;
        float w = w2[e];
        int f = e / 32;
        dcls_scatter(g_K2 + f * 36, w, p2[e], p2[65536 + e]);
    }
}

__global__ void repack_all(const float* __restrict__ W) {
    int i = blockIdx.x * blockDim.x + threadIdx.x;
    if (i < 1024) {
        int oc = i >> 5, t = i & 31;
        float w = (t < 25) ? g_K1[oc * 36 + (t / 5) * 6 + (t % 5)] : 0.f;
        g_W1t[i] = __float2half(w);
    }
    if (i < 51200) {
        int t = i / 2048, r = i % 2048;
        int oc = r >> 5, ic = r & 31;
        float w = g_K2[(oc * 32 + ic) * 36 + (t / 5) * 6 + (t % 5)];
        g_W2t[i] = __float2half(w);
    }
    if (i < 128 * 3136) g_F1h[i] = __float2half(W[i]);
}

// ---------------- fused conv1 + pool + conv2 + pool ------------------------
// CTA = 1 image, 256 thr (8 warps = 4 m-quadrants x 2 n-halves).
// SMEM: Xpad@0 (2048) | W1@2048 (2560) | A 8x1280@4608 | X2@14848 (25920) |
//   W2 3-buf@40768 (15360). Total 56128. Epilogue P (50688) reuses @0.

#define XP_OFF   0
#define W1_OFF   2048
#define A_OFF    4608
#define X2_OFF   14848
#define W2_OFF   40768
#define WROWB    80
#define WTAP     (64 * WROWB)                // 5120
#define C2_SMEM  56128

__global__ __launch_bounds__(256, 2) void fused_conv(const float* __restrict__ x,
                                                     const float* __restrict__ b1,
                                                     const float* __restrict__ b2) {
    extern __shared__ __align__(16) char dsm[];
    __shared__ float sB1[32];
    uint32_t Su = smem_u32(dsm);

    int tid = threadIdx.x;
    int w = tid >> 5, l = tid & 31;
    int wm = w & 3, wn = w >> 2;
    int b = blockIdx.x;

    // zero Xpad..X2 (covers padding borders)
    for (int i = tid; i < W2_OFF / 16; i += 256)
        ((uint4*)dsm)[i] = make_uint4(0u, 0u, 0u, 0u);
    // stage conv2 tap-0 weights
    {
        const char* src = (const char*)g_W2t;
        int r = tid >> 2, c = tid & 3;
        cp_async16(Su + W2_OFF + (uint32_t)(r * WROWB + c * 16), src + r * 64 + c * 16);
        CP_COMMIT();
    }
    if (tid < 32) sB1[tid] = b1[tid];
    __syncthreads();

    // fill Xpad fp16 and W1
    const float* xi = x + (size_t)b * 784;
    for (int i = tid; i < 784; i += 256) {
        int y = i / 28, c = i % 28;
        *((__half*)(dsm + XP_OFF) + (y + 2) * 32 + c + 2) = __float2half(xi[i]);
    }
    {
        const uint32_t* w1s = (const uint32_t*)g_W1t;     // 512 u32
        for (int i = tid; i < 512; i += 256) {
            int r = i >> 4, c = i & 15;
            *(uint32_t*)(dsm + W1_OFF + r * 80 + c * 4) = w1s[i];
        }
    }
    __syncthreads();

    // ---- conv1 phase: 49 m16 tiles (784 sites) spread over 8 warps ----
    {
        uint32_t AwB = (uint32_t)(A_OFF + w * 1280);
        uint32_t AwU = Su + AwB;
        const __half* XPh = (const __half*)(dsm + XP_OFF);

        for (int T = w; T < 49; T += 8) {
            for (int j = l; j < 80; j += 32) {
                int sl = j / 5, dy = j % 5;
                int sp = T * 16 + sl;
                int p = sp >> 2, sub = sp & 3;
                int y = 2 * (p / 14) + (sub >> 1);
                int xx = 2 * (p % 14) + (sub & 1);
                const __half* sr = XPh + (y + dy) * 32 + xx;
                __half* dr = (__half*)(dsm + AwB + sl * 80) + dy * 5;
                dr[0] = sr[0]; dr[1] = sr[1]; dr[2] = sr[2]; dr[3] = sr[3]; dr[4] = sr[4];
            }
            __syncwarp();
            uint32_t a0[4], a1[4];
            ldmx4(a0, AwU + (uint32_t)((l & 15) * 80 + (l >> 4) * 16));
            ldmx4(a1, AwU + (uint32_t)((l & 15) * 80 + 32 + (l >> 4) * 16));
            __syncwarp();

#pragma unroll
            for (int n = 0; n < 4; n++) {
                const char* wr = dsm + W1_OFF + (n * 8 + (l >> 2)) * 80 + (l & 3) * 4;
                uint32_t b0[2] = { *(const uint32_t*)wr, *(const uint32_t*)(wr + 16) };
                uint32_t b1f[2] = { *(const uint32_t*)(wr + 32), *(const uint32_t*)(wr + 48) };
                float acc[4] = {0.f, 0.f, 0.f, 0.f};
                mma16816(acc, a0, b0);
                mma16816(acc, a1, b1f);
                float c0 = rmax4(acc[0]), c1 = rmax4(acc[1]);
                float c2 = rmax4(acc[2]), c3 = rmax4(acc[3]);
                if ((l & 12) == 0) {
                    int oc0 = n * 8 + 2 * (l & 3);
                    float bb0 = sB1[oc0], bb1 = sB1[oc0 + 1];
                    int qa = 4 * T + (l >> 4);
                    int qb = qa + 2;
                    int ga = (qa / 14 + 2) * 18 + (qa % 14) + 2;
                    int gb = (qb / 14 + 2) * 18 + (qb % 14) + 2;
                    __half2 ha = __floats2half2_rn(fmaxf(c0 + bb0, 0.f), fmaxf(c1 + bb1, 0.f));
                    __half2 hb = __floats2half2_rn(fmaxf(c2 + bb0, 0.f), fmaxf(c3 + bb1, 0.f));
                    *(__half2*)(dsm + X2_OFF + ga * 80 + 2 * oc0) = ha;
                    *(__half2*)(dsm + X2_OFF + gb * 80 + 2 * oc0) = hb;
                }
            }
        }
    }
    __syncthreads();

    // ---- conv2 phase: warp (wm, wn) -> m-tiles wm*4+mi, n-tiles wn*4+n ----
    uint32_t Xu = Su + X2_OFF;
    uint32_t Wu = Su + W2_OFF;

    int row = l & 15, kh = l >> 4;
    uint32_t aBase[4];
#pragma unroll
    for (int mi = 0; mi < 4; mi++) {
        int s = (wm * 4 + mi) * 16 + row;
        if (s > 195) s = 0;
        int g0 = (s / 14) * 18 + (s % 14);
        aBase[mi] = Xu + (uint32_t)g0 * 80 + (uint32_t)kh * 16;
    }
    uint32_t bOff = (uint32_t)((wn * 32 + (l >> 2)) * WROWB + (l & 3) * 4);

    float acc[4][4][4];
#pragma unroll
    for (int mi = 0; mi < 4; mi++)
#pragma unroll
        for (int n = 0; n < 4; n++)
#pragma unroll
            for (int k = 0; k < 4; k++) acc[mi][n][k] = 0.f;

    for (int t = 0; t < 25; t++) {
        if (t < 24) {
            const char* src = (const char*)(g_W2t + (t + 1) * 2048);
            uint32_t wdst = Wu + (uint32_t)(((t + 1) % 3) * WTAP);
            int r = tid >> 2, c = tid & 3;
            cp_async16(wdst + (uint32_t)(r * WROWB + c * 16), src + r * 64 + c * 16);
            CP_COMMIT();
            CP_WAIT1();
        } else {
            CP_WAIT0();
        }
        __syncthreads();

        uint32_t wb = Wu + (uint32_t)((t % 3) * WTAP);
        uint32_t doff = (uint32_t)((t / 5) * 18 + (t % 5)) * 80;

#pragma unroll
        for (int kc = 0; kc < 2; kc++) {
            uint32_t ah[4][4];
#pragma unroll
            for (int mi = 0; mi < 4; mi++)
                ldmx4(ah[mi], aBase[mi] + doff + kc * 32);
            uint32_t bh_base = wb + bOff + (uint32_t)(kc * 32);
#pragma unroll
            for (int n = 0; n < 4; n++) {
                uint32_t o = (uint32_t)n * (8 * WROWB);
                uint32_t bh[2];
                bh[0] = *(const uint32_t*)(dsm + (bh_base + o - Su));
                bh[1] = *(const uint32_t*)(dsm + (bh_base + o + 16 - Su));
#pragma unroll
                for (int mi = 0; mi < 4; mi++)
                    mma16816(acc[mi][n], ah[mi], bh);
            }
        }
    }
    __syncthreads();

    // ---- epilogue: acc -> prepool P -> pool+bias+relu -> h2 fp16 ----
    float* P = (float*)dsm;                  // [64 oc][198]
    int r = l >> 2, c2 = l & 3;
#pragma unroll
    for (int mi = 0; mi < 4; mi++) {
        int s0 = (wm * 4 + mi) * 16 + r;
        int s1 = s0 + 8;
#pragma unroll
        for (int n = 0; n < 4; n++) {
            int oc0 = (wn * 4 + n) * 8 + 2 * c2;
            if (s0 < 196) {
                P[oc0 * 198 + s0] = acc[mi][n][0];
                P[(oc0 + 1) * 198 + s0] = acc[mi][n][1];
            }
            if (s1 < 196) {
                P[oc0 * 198 + s1] = acc[mi][n][2];
                P[(oc0 + 1) * 198 + s1] = acc[mi][n][3];
            }
        }
    }
    __syncthreads();
    for (int j = tid; j < 3136; j += 256) {
        int oc = j / 49, q = j % 49;
        int py = q / 7, px = q % 7;
        const float* pp = P + oc * 198 + (2 * py) * 14 + 2 * px;
        float v = fmaxf(fmaxf(pp[0], pp[1]), fmaxf(pp[14], pp[15]));
        g_h2h[(size_t)b * 3136 + j] = __float2half(fmaxf(v + b2[oc], 0.f));
    }
}

// ---------------- FC1 (M=32, N=128, pure fp16) + fused FC2 -----------------

#define F1ROW  144
#define F1BUF  ((32 + 128) * F1ROW)          // 23040
#define FC1_SMEM (3 * F1BUF)                 // 69120

__global__ __launch_bounds__(256, 2) void fc1_fused(
        const float* __restrict__ bias, const float* __restrict__ W2,
        const float* __restrict__ b2f, float* __restrict__ out) {
    extern __shared__ __align__(16) char fsm[];
    __shared__ float sW2[1280];
    __shared__ float sB2[10];
    __shared__ float sBias[128];
    uint32_t Su = smem_u32(fsm);

    int tid = threadIdx.x;
    int w = tid >> 5, l = tid & 31;
    int wm = w >> 2, wn = w & 3;
    int m0 = blockIdx.x * 32;

    for (int i = tid; i < 1280; i += 256) sW2[i] = W2[i];
    if (tid < 10) sB2[tid] = b2f[tid];
    if (tid < 128) sBias[tid] = bias[tid];

    float acc[4][4];
#pragma unroll
    for (int nt = 0; nt < 4; nt++)
#pragma unroll
        for (int k = 0; k < 4; k++) acc[nt][k] = 0.f;

    auto stage = [&](int kt, int buf) {
        uint32_t dst0 = Su + (uint32_t)(buf * F1BUF);
        int k0 = kt * 64;
#pragma unroll
        for (int i = 0; i < 5; i++) {
            int j = tid + 256 * i;
            int rrow = j >> 3, c = j & 7;
            const __half* src = (rrow < 32)
                ? g_h2h + (size_t)(m0 + rrow) * 3136 + k0 + c * 8
                : g_F1h + (size_t)(rrow - 32) * 3136 + k0 + c * 8;
            cp_async16(dst0 + (uint32_t)(rrow * F1ROW + c * 16), src);
        }
        CP_COMMIT();
    };

    stage(0, 0);

    uint32_t aOff = (uint32_t)((wm * 16 + (l & 15)) * F1ROW + (l >> 4) * 16);
    uint32_t bRow = (uint32_t)(32 + wn * 32 + (l >> 2));
    uint32_t bW0 = (uint32_t)((l & 3) * 4);

    for (int kt = 0; kt < 49; kt++) {
        if (kt < 48) { stage(kt + 1, (kt + 1) % 3); CP_WAIT1(); }
        else CP_WAIT0();
        __syncthreads();
        uint32_t bufo = (uint32_t)((kt % 3) * F1BUF);

#pragma unroll
        for (int kc = 0; kc < 4; kc++) {
            uint32_t ah[4];
            ldmx4(ah, Su + bufo + aOff + kc * 32);
#pragma unroll
            for (int nt = 0; nt < 4; nt++) {
                uint32_t rb = bufo + (bRow + nt * 8) * F1ROW + bW0 + kc * 32;
                uint32_t bh[2];
                bh[0] = *(const uint32_t*)(fsm + rb);
                bh[1] = *(const uint32_t*)(fsm + rb + 16);
                mma16816(acc[nt], ah, bh);
            }
        }
        __syncthreads();
    }

    float* hP = (float*)fsm;                 // [32][132]
    int r0 = wm * 16 + (l >> 2);
#pragma unroll
    for (int nt = 0; nt < 4; nt++) {
        int col = wn * 32 + nt * 8 + 2 * (l & 3);
        float bs0 = sBias[col], bs1 = sBias[col + 1];
        hP[r0 * 132 + col]       = fmaxf(acc[nt][0] + bs0, 0.f);
        hP[r0 * 132 + col + 1]   = fmaxf(acc[nt][1] + bs1, 0.f);
        hP[(r0 + 8) * 132 + col]     = fmaxf(acc[nt][2] + bs0, 0.f);
        hP[(r0 + 8) * 132 + col + 1] = fmaxf(acc[nt][3] + bs1, 0.f);
    }
    __syncthreads();

    for (int it = tid; it < 320; it += 256) {
        int r = it / 10, o = it % 10;
        const float* hr = hP + r * 132;
        const float* wr = sW2 + o * 128;
        float s = 0.f;
#pragma unroll
        for (int c = 0; c < 128; c++) s += hr[c] * wr[c];
        out[(size_t)(m0 + r) * 10 + o] = s + sB2[o];
    }
}

// ---------------------------------------------------------------------------

extern "C" void kernel_launch(void* const* d_in, const int* in_sizes, int n_in,
                              void* d_out, int out_size) {
    const float* x    = (const float*)d_in[0];
    const float* w1   = (const float*)d_in[1];
    const float* p1   = (const float*)d_in[2];
    const float* b1   = (const float*)d_in[3];
    const float* w2   = (const float*)d_in[4];
    const float* p2   = (const float*)d_in[5];
    const float* b2   = (const float*)d_in[6];
    const float* fc1w = (const float*)d_in[7];
    const float* fc1b = (const float*)d_in[8];
    const float* fc2w = (const float*)d_in[9];
    const float* fc2b = (const float*)d_in[10];
    float* out = (float*)d_out;

    int B = in_sizes[0] / 784;
    if (B > B_MAX) B = B_MAX;

    zero_k<<<(64 * 32 * 36 + 255) / 256, 256>>>();
    build_k<<<(512 + 65536 + 255) / 256, 256>>>(w1, p1, w2, p2);
    repack_all<<<(128 * 3136 + 255) / 256, 256>>>(fc1w);

    cudaFuncSetAttribute(fused_conv, cudaFuncAttributeMaxDynamicSharedMemorySize, C2_SMEM);
    fused_conv<<<B, 256, C2_SMEM>>>(x, b1, b2);

    cudaFuncSetAttribute(fc1_fused, cudaFuncAttributeMaxDynamicSharedMemorySize, FC1_SMEM);
    fc1_fused<<<B / 32, 256, FC1_SMEM>>>(fc1b, fc2w, fc2b, out);
}